// round 1
// baseline (speedup 1.0000x reference)
#include <cuda_runtime.h>

#define NB   64    // blocks per sequence
#define BS   64    // block size S
#define DD   64
#define FF   64
#define F2   128
#define HH   16
#define LL   4096
#define BBQ  2
#define BH   32
#define EPSV 1e-6f

// scratch: per-block state deltas, converted in-place to exclusive prefixes
__device__ float g_dS[(size_t)BH * NB * F2 * DD];  // 67 MB
__device__ float g_dZ[(size_t)BH * NB * F2];       // 1 MB

__device__ __forceinline__ float wmax(float x) {
#pragma unroll
    for (int o = 16; o; o >>= 1) x = fmaxf(x, __shfl_xor_sync(0xffffffffu, x, o));
    return x;
}
__device__ __forceinline__ float wsum(float x) {
#pragma unroll
    for (int o = 16; o; o >>= 1) x += __shfl_xor_sync(0xffffffffu, x, o);
    return x;
}

// u = X @ W (64x64 @ 64x64), then phi = [softmax(u), softmax(-u)] -> sPhi (64x128)
// Caller must __syncthreads() before (sX, sW ready) and after (sPhi ready).
__device__ __forceinline__ void feature_map(const float* __restrict__ sX,
                                            const float* __restrict__ sW,
                                            float* __restrict__ sU,
                                            float* __restrict__ sPhi, int t) {
    int s0 = (t >> 4) * 4, f0 = (t & 15) * 4;
    float acc[4][4] = {};
#pragma unroll 4
    for (int d = 0; d < 64; d++) {
        float4 wv = *(const float4*)&sW[d * 64 + f0];
#pragma unroll
        for (int i = 0; i < 4; i++) {
            float xv = sX[(s0 + i) * 64 + d];
            acc[i][0] += xv * wv.x;
            acc[i][1] += xv * wv.y;
            acc[i][2] += xv * wv.z;
            acc[i][3] += xv * wv.w;
        }
    }
#pragma unroll
    for (int i = 0; i < 4; i++) {
        float4 o = make_float4(acc[i][0], acc[i][1], acc[i][2], acc[i][3]);
        *(float4*)&sU[(s0 + i) * 64 + f0] = o;
    }
    __syncthreads();
    int warp = t >> 5, lane = t & 31;
#pragma unroll
    for (int r = 0; r < 8; r++) {
        int s = warp * 8 + r;
        float v0 = sU[s * 64 + lane];
        float v1 = sU[s * 64 + 32 + lane];
        float hi = wmax(fmaxf(v0, v1));
        float lo = -wmax(fmaxf(-v0, -v1));
        float e0 = __expf(v0 - hi), e1 = __expf(v1 - hi);
        float sp = wsum(e0 + e1);
        float g0 = __expf(lo - v0), g1 = __expf(lo - v1);
        float sn = wsum(g0 + g1);
        float rp = 1.f / sp, rn = 1.f / sn;
        sPhi[s * 128 + lane]      = e0 * rp;
        sPhi[s * 128 + 32 + lane] = e1 * rp;
        sPhi[s * 128 + 64 + lane] = g0 * rn;
        sPhi[s * 128 + 96 + lane] = g1 * rn;
    }
}

// ---------------- Phase 1: per-block deltas dS = phi_k^T v, dZ = sum phi_k --------
__global__ void __launch_bounds__(256, 2)
phase1_kernel(const float* __restrict__ K, const float* __restrict__ V,
              const float* __restrict__ W) {
    extern __shared__ float smem[];
    float* sW   = smem;            // 4096
    float* sK   = sW + 4096;       // 4096
    float* sU   = sK + 4096;       // 4096
    float* sV   = sU + 4096;       // 4096
    float* sPhi = sV + 4096;       // 8192  -> 24576 floats = 96 KB

    int t = threadIdx.x;
    int bid = blockIdx.x, bh = bid >> 6, n = bid & 63, h = bh & (HH - 1);
    size_t xb = ((size_t)bh * LL + (size_t)n * BS) * DD;

    for (int i = t; i < 4096; i += 256) {
        sW[i] = W[h * 4096 + i];
        sK[i] = K[xb + i];
        sV[i] = V[xb + i];
    }
    __syncthreads();
    feature_map(sK, sW, sU, sPhi, t);
    __syncthreads();

    // dS[f][d] = sum_s phi[s][f] * v[s][d]
    int f0 = (t >> 4) * 8, d0 = (t & 15) * 4;
    float acc[8][4] = {};
#pragma unroll 2
    for (int s = 0; s < 64; s++) {
        float4 vv = *(const float4*)&sV[s * 64 + d0];
#pragma unroll
        for (int i = 0; i < 8; i++) {
            float p = sPhi[s * 128 + f0 + i];
            acc[i][0] += p * vv.x;
            acc[i][1] += p * vv.y;
            acc[i][2] += p * vv.z;
            acc[i][3] += p * vv.w;
        }
    }
    size_t sb = (size_t)(bh * NB + n) * F2 * DD;
#pragma unroll
    for (int i = 0; i < 8; i++) {
        float4 o = make_float4(acc[i][0], acc[i][1], acc[i][2], acc[i][3]);
        *(float4*)&g_dS[sb + (size_t)(f0 + i) * 64 + d0] = o;
    }
    if (t < 128) {
        float z = 0.f;
#pragma unroll 4
        for (int s = 0; s < 64; s++) z += sPhi[s * 128 + t];
        g_dZ[(size_t)(bh * NB + n) * F2 + t] = z;
    }
}

// ---------------- Exclusive prefix scans over n (in-place) -----------------------
__global__ void scanS_kernel() {
    int bh = blockIdx.y;
    int e = blockIdx.x * 256 + threadIdx.x;  // 0..8191
    size_t base = (size_t)bh * NB * 8192 + e;
    float run = 0.f;
#pragma unroll 4
    for (int n = 0; n < NB; n++) {
        float x = g_dS[base + (size_t)n * 8192];
        g_dS[base + (size_t)n * 8192] = run;
        run += x;
    }
}

__global__ void scanZ_kernel() {
    int bh = blockIdx.x;
    int f = threadIdx.x;  // 0..127
    size_t base = (size_t)bh * NB * F2 + f;
    float run = 0.f;
#pragma unroll 4
    for (int n = 0; n < NB; n++) {
        float x = g_dZ[base + (size_t)n * F2];
        g_dZ[base + (size_t)n * F2] = run;
        run += x;
    }
}

// ---------------- Phase 2: outputs ------------------------------------------------
__global__ void __launch_bounds__(256, 2)
phase2_kernel(const float* __restrict__ Q, const float* __restrict__ K,
              const float* __restrict__ V, const float* __restrict__ W,
              const float* __restrict__ alpha, float* __restrict__ out) {
    extern __shared__ float smem[];
    float* sQ   = smem;            // 4096 (later reused as the exp-score matrix a)
    float* sSt  = sQ + 4096;       // 8192 (first: W in [0:4096], u in [4096:8192]; then S prefix)
    float* sPhi = sSt + 8192;      // 8192
    float* sKT  = sPhi + 8192;     // 4096 (rotation-swizzled k^T; [0:64] reused for dens)
    float* sV   = sKT + 4096;      // 4096  -> 28672 floats = 112 KB

    int t = threadIdx.x, warp = t >> 5, lane = t & 31;
    int bid = blockIdx.x, bh = bid >> 6, n = bid & 63, h = bh & (HH - 1);
    size_t xb = ((size_t)bh * LL + (size_t)n * BS) * DD;

    float* sW = sSt;
    float* sU = sSt + 4096;
    for (int i = t; i < 4096; i += 256) {
        sW[i] = W[h * 4096 + i];
        sQ[i] = Q[xb + i];
    }
    __syncthreads();
    feature_map(sQ, sW, sU, sPhi, t);
    __syncthreads();

    // load S prefix, k (transposed+rotated), v
    size_t sb = (size_t)(bh * NB + n) * F2 * DD;
    for (int i = t; i < 8192; i += 256) sSt[i] = g_dS[sb + i];
    for (int i = t; i < 4096; i += 256) {
        int s = i >> 6, d = i & 63;
        sKT[d * 64 + ((s + d) & 63)] = K[xb + i];
        sV[i] = V[xb + i];
    }
    __syncthreads();

    float wgt = 1.f / (1.f + __expf(-alpha[h]));

    // lin_den (regs) + intra-block scores + softmax; a overlays sQ
    size_t zb = (size_t)(bh * NB + n) * F2;
    float z0 = g_dZ[zb + lane], z1 = g_dZ[zb + 32 + lane];
    float z2 = g_dZ[zb + 64 + lane], z3 = g_dZ[zb + 96 + lane];
    float dreg[8];
#pragma unroll
    for (int r = 0; r < 8; r++) {
        int s = warp * 8 + r;
        float ld = sPhi[s * 128 + lane] * z0 + sPhi[s * 128 + 32 + lane] * z1 +
                   sPhi[s * 128 + 64 + lane] * z2 + sPhi[s * 128 + 96 + lane] * z3;
        ld = fmaxf(wsum(ld), EPSV);

        float sc0 = 0.f, sc1 = 0.f;
#pragma unroll 4
        for (int d = 0; d < 64; d++) {
            float qv = sQ[s * 64 + d];
            sc0 += qv * sKT[d * 64 + ((lane + d) & 63)];
            sc1 += qv * sKT[d * 64 + ((lane + 32 + d) & 63)];
        }
        sc0 *= 0.125f;
        sc1 *= 0.125f;
        float m = wmax(fmaxf(sc0, sc1));
        float a0 = __expf(sc0 - m), a1 = __expf(sc1 - m);
        float asum = fmaxf(wsum(a0 + a1), EPSV);
        dreg[r] = fmaxf(wgt * asum + ld, EPSV);
        // shfl syncs above guarantee all q reads of row s are done before this write
        sQ[s * 64 + lane] = a0;
        sQ[s * 64 + 32 + lane] = a1;
    }
    __syncthreads();
#pragma unroll
    for (int r = 0; r < 8; r++)
        if (lane == r) sKT[warp * 8 + r] = dreg[r];
    __syncthreads();

    // fused GEMMs: lin = phi_q @ S  and  sm = a @ v
    int s0 = (t >> 4) * 4, d0 = (t & 15) * 4;
    float lacc[4][4] = {}, sacc[4][4] = {};
#pragma unroll 2
    for (int f = 0; f < 128; f++) {
        float4 sv = *(const float4*)&sSt[f * 64 + d0];
#pragma unroll
        for (int i = 0; i < 4; i++) {
            float p = sPhi[(s0 + i) * 128 + f];
            lacc[i][0] += p * sv.x;
            lacc[i][1] += p * sv.y;
            lacc[i][2] += p * sv.z;
            lacc[i][3] += p * sv.w;
        }
    }
#pragma unroll 2
    for (int tt = 0; tt < 64; tt++) {
        float4 vv = *(const float4*)&sV[tt * 64 + d0];
#pragma unroll
        for (int i = 0; i < 4; i++) {
            float a = sQ[(s0 + i) * 64 + tt];
            sacc[i][0] += a * vv.x;
            sacc[i][1] += a * vv.y;
            sacc[i][2] += a * vv.z;
            sacc[i][3] += a * vv.w;
        }
    }
#pragma unroll
    for (int i = 0; i < 4; i++) {
        int s = s0 + i;
        float rden = 1.f / sKT[s];
        float4 o;
        o.x = (wgt * sacc[i][0] + lacc[i][0]) * rden;
        o.y = (wgt * sacc[i][1] + lacc[i][1]) * rden;
        o.z = (wgt * sacc[i][2] + lacc[i][2]) * rden;
        o.w = (wgt * sacc[i][3] + lacc[i][3]) * rden;
        *(float4*)&out[xb + (size_t)s * 64 + d0] = o;
    }
}

extern "C" void kernel_launch(void* const* d_in, const int* in_sizes, int n_in,
                              void* d_out, int out_size) {
    const float* Q = (const float*)d_in[0];
    const float* K = (const float*)d_in[1];
    const float* V = (const float*)d_in[2];
    const float* W = (const float*)d_in[3];
    const float* A = (const float*)d_in[4];
    float* out = (float*)d_out;

    cudaFuncSetAttribute(phase1_kernel, cudaFuncAttributeMaxDynamicSharedMemorySize, 98304);
    cudaFuncSetAttribute(phase2_kernel, cudaFuncAttributeMaxDynamicSharedMemorySize, 114688);

    phase1_kernel<<<BH * NB, 256, 98304>>>(K, V, W);
    scanS_kernel<<<dim3(32, BH), 256>>>();
    scanZ_kernel<<<BH, 128>>>();
    phase2_kernel<<<BH * NB, 256, 114688>>>(Q, K, V, W, A, out);
}

// round 2
// speedup vs baseline: 1.2198x; 1.2198x over previous
#include <cuda_runtime.h>

#define NB   64
#define BS   64
#define F2   128
#define HH   16
#define LL   4096
#define BH   32
#define EPSV 1e-6f

__device__ float g_dS[(size_t)BH * NB * F2 * 64];  // 67 MB scratch
__device__ float g_dZ[(size_t)BH * NB * F2];       // 1 MB

__device__ __forceinline__ float wmax(float x) {
#pragma unroll
    for (int o = 16; o; o >>= 1) x = fmaxf(x, __shfl_xor_sync(0xffffffffu, x, o));
    return x;
}
__device__ __forceinline__ float wsum(float x) {
#pragma unroll
    for (int o = 16; o; o >>= 1) x += __shfl_xor_sync(0xffffffffu, x, o);
    return x;
}

// acc[i][j] += sum_k A[(r0+i)*LDA + k] * B[k*LDB + c0+j], k-blocked x4, float4 both sides
template<int KDIM, int LDA, int LDB>
__device__ __forceinline__ void mm4x4(const float* __restrict__ A, const float* __restrict__ B,
                                      float (&acc)[4][4], int r0, int c0) {
#pragma unroll
    for (int k0 = 0; k0 < KDIM; k0 += 4) {
        float4 av[4], bv[4];
#pragma unroll
        for (int i = 0; i < 4; i++) av[i] = *(const float4*)&A[(r0 + i) * LDA + k0];
#pragma unroll
        for (int j = 0; j < 4; j++) bv[j] = *(const float4*)&B[(k0 + j) * LDB + c0];
#pragma unroll
        for (int i = 0; i < 4; i++) {
            acc[i][0] += av[i].x * bv[0].x + av[i].y * bv[1].x + av[i].z * bv[2].x + av[i].w * bv[3].x;
            acc[i][1] += av[i].x * bv[0].y + av[i].y * bv[1].y + av[i].z * bv[2].y + av[i].w * bv[3].y;
            acc[i][2] += av[i].x * bv[0].z + av[i].y * bv[1].z + av[i].z * bv[2].z + av[i].w * bv[3].z;
            acc[i][3] += av[i].x * bv[0].w + av[i].y * bv[1].w + av[i].z * bv[2].w + av[i].w * bv[3].w;
        }
    }
}

// Same but B columns are XOR-swizzled: element B[k][c] lives at k*64 + (c ^ ((k&7)<<2)).
__device__ __forceinline__ void mm4x4_kswz(const float* __restrict__ A, const float* __restrict__ B,
                                           float (&acc)[4][4], int r0, int c0) {
#pragma unroll
    for (int k0 = 0; k0 < 64; k0 += 4) {
        float4 av[4], bv[4];
#pragma unroll
        for (int i = 0; i < 4; i++) av[i] = *(const float4*)&A[(r0 + i) * 64 + k0];
#pragma unroll
        for (int j = 0; j < 4; j++)
            bv[j] = *(const float4*)&B[(k0 + j) * 64 + (c0 ^ (((k0 + j) & 7) << 2))];
#pragma unroll
        for (int i = 0; i < 4; i++) {
            acc[i][0] += av[i].x * bv[0].x + av[i].y * bv[1].x + av[i].z * bv[2].x + av[i].w * bv[3].x;
            acc[i][1] += av[i].x * bv[0].y + av[i].y * bv[1].y + av[i].z * bv[2].y + av[i].w * bv[3].y;
            acc[i][2] += av[i].x * bv[0].z + av[i].y * bv[1].z + av[i].z * bv[2].z + av[i].w * bv[3].z;
            acc[i][3] += av[i].x * bv[0].w + av[i].y * bv[1].w + av[i].z * bv[2].w + av[i].w * bv[3].w;
        }
    }
}

// u = X @ W, phi = [softmax(u), softmax(-u)] -> sPhi (64x128).
// Callers sync before (sX,sW ready) and after (sPhi ready).
__device__ __forceinline__ void feature_map(const float* __restrict__ sX,
                                            const float* __restrict__ sW,
                                            float* __restrict__ sU,
                                            float* __restrict__ sPhi, int t) {
    int s0 = (t >> 4) * 4, f0 = (t & 15) * 4;
    float acc[4][4] = {};
    mm4x4<64, 64, 64>(sX, sW, acc, s0, f0);
#pragma unroll
    for (int i = 0; i < 4; i++)
        *(float4*)&sU[(s0 + i) * 64 + f0] = make_float4(acc[i][0], acc[i][1], acc[i][2], acc[i][3]);
    __syncthreads();
    int warp = t >> 5, lane = t & 31;
#pragma unroll
    for (int r = 0; r < 8; r++) {
        int s = warp * 8 + r;
        float v0 = sU[s * 64 + lane];
        float v1 = sU[s * 64 + 32 + lane];
        float hi = wmax(fmaxf(v0, v1));
        float lo = -wmax(fmaxf(-v0, -v1));
        float e0 = __expf(v0 - hi), e1 = __expf(v1 - hi);
        float sp = wsum(e0 + e1);
        float g0 = __expf(lo - v0), g1 = __expf(lo - v1);
        float sn = wsum(g0 + g1);
        float rp = 1.f / sp, rn = 1.f / sn;
        sPhi[s * 128 + lane]      = e0 * rp;
        sPhi[s * 128 + 32 + lane] = e1 * rp;
        sPhi[s * 128 + 64 + lane] = g0 * rn;
        sPhi[s * 128 + 96 + lane] = g1 * rn;
    }
}

// ---------------- Phase 1: dS = phi_k^T v, dZ = sum_s phi_k -----------------------
__global__ void __launch_bounds__(256, 2)
phase1_kernel(const float* __restrict__ K, const float* __restrict__ V,
              const float* __restrict__ W) {
    extern __shared__ float smem[];
    float* sW   = smem;         // 4096
    float* sK   = sW + 4096;    // 4096
    float* sU   = sK + 4096;    // 4096
    float* sV   = sU + 4096;    // 4096
    float* sPhi = sV + 4096;    // 8192   -> 96 KB

    int t = threadIdx.x;
    int bid = blockIdx.x, bh = bid >> 6, n = bid & 63, h = bh & (HH - 1);
    size_t xb = ((size_t)bh * LL + (size_t)n * BS) * 64;

    for (int i = t; i < 4096; i += 256) {
        sW[i] = W[h * 4096 + i];
        sK[i] = K[xb + i];
        sV[i] = V[xb + i];
    }
    __syncthreads();
    feature_map(sK, sW, sU, sPhi, t);
    __syncthreads();

    // dS[f][d] = sum_s phi[s][f] * v[s][d]   (8x4 tile per thread)
    int f0 = (t >> 4) * 8, d0 = (t & 15) * 4;
    float acc[8][4] = {};
#pragma unroll 4
    for (int s = 0; s < 64; s++) {
        float4 vv = *(const float4*)&sV[s * 64 + d0];
        float4 p0 = *(const float4*)&sPhi[s * 128 + f0];
        float4 p1 = *(const float4*)&sPhi[s * 128 + f0 + 4];
        float p[8] = {p0.x, p0.y, p0.z, p0.w, p1.x, p1.y, p1.z, p1.w};
#pragma unroll
        for (int i = 0; i < 8; i++) {
            acc[i][0] += p[i] * vv.x;
            acc[i][1] += p[i] * vv.y;
            acc[i][2] += p[i] * vv.z;
            acc[i][3] += p[i] * vv.w;
        }
    }
    size_t sb = (size_t)(bh * NB + n) * F2 * 64;
#pragma unroll
    for (int i = 0; i < 8; i++)
        *(float4*)&g_dS[sb + (size_t)(f0 + i) * 64 + d0] =
            make_float4(acc[i][0], acc[i][1], acc[i][2], acc[i][3]);
    if (t < 128) {
        float z = 0.f;
#pragma unroll 8
        for (int s = 0; s < 64; s++) z += sPhi[s * 128 + t];
        g_dZ[(size_t)(bh * NB + n) * F2 + t] = z;
    }
}

// ---------------- Exclusive prefix scans over n (in-place) ------------------------
__global__ void scanS_kernel() {
    int bh = blockIdx.y;
    int e = blockIdx.x * 256 + threadIdx.x;
    size_t base = (size_t)bh * NB * 8192 + e;
    float run = 0.f;
#pragma unroll 8
    for (int n = 0; n < NB; n++) {
        float x = g_dS[base + (size_t)n * 8192];
        g_dS[base + (size_t)n * 8192] = run;
        run += x;
    }
}

__global__ void scanZ_kernel() {
    int bh = blockIdx.x;
    int f = threadIdx.x;
    size_t base = (size_t)bh * NB * F2 + f;
    float run = 0.f;
#pragma unroll 8
    for (int n = 0; n < NB; n++) {
        float x = g_dZ[base + (size_t)n * F2];
        g_dZ[base + (size_t)n * F2] = run;
        run += x;
    }
}

// ---------------- Phase 2: outputs ------------------------------------------------
__global__ void __launch_bounds__(256, 2)
phase2_kernel(const float* __restrict__ Q, const float* __restrict__ K,
              const float* __restrict__ V, const float* __restrict__ W,
              const float* __restrict__ alpha, float* __restrict__ out) {
    extern __shared__ float smem[];
    float* sQ   = smem;          // 4096: q, then exp-scores a
    float* sSt  = sQ + 4096;     // 8192: [W | u] during feature_map, then S prefix
    float* sPhi = sSt + 8192;    // 8192
    float* sKT  = sPhi + 8192;   // 4096: swizzled k^T; [0:64] reused as den
    float* sV   = sKT + 4096;    // 4096   -> 112 KB

    int t = threadIdx.x, warp = t >> 5, lane = t & 31;
    int bid = blockIdx.x, bh = bid >> 6, n = bid & 63, h = bh & (HH - 1);
    size_t xb = ((size_t)bh * LL + (size_t)n * BS) * 64;

    float* sW = sSt;
    float* sU = sSt + 4096;
    for (int i = t; i < 4096; i += 256) {
        sW[i] = W[h * 4096 + i];
        sQ[i] = Q[xb + i];
    }
    __syncthreads();
    feature_map(sQ, sW, sU, sPhi, t);
    __syncthreads();

    size_t sb = (size_t)(bh * NB + n) * F2 * 64;
    for (int i = t; i < 8192; i += 256) sSt[i] = g_dS[sb + i];
    for (int i = t; i < 4096; i += 256) {
        int s = i >> 6, d = i & 63;
        sKT[d * 64 + (s ^ ((d & 7) << 2))] = K[xb + i];  // k^T, XOR-swizzled columns
        sV[i] = V[xb + i];
    }
    __syncthreads();

    float wgt = 1.f / (1.f + __expf(-alpha[h]));

    // GEMM1: scores = q @ k^T (accumulate in regs, then overwrite sQ)
    int s0 = (t >> 4) * 4, c0 = (t & 15) * 4;
    float acc[4][4] = {};
    mm4x4_kswz(sQ, sKT, acc, s0, c0);
    __syncthreads();   // all reads of sQ / sKT done
#pragma unroll
    for (int i = 0; i < 4; i++)
        *(float4*)&sQ[(s0 + i) * 64 + c0] =
            make_float4(acc[i][0] * 0.125f, acc[i][1] * 0.125f, acc[i][2] * 0.125f, acc[i][3] * 0.125f);
    __syncwarp();      // score rows 8w..8w+7 are produced & consumed by warp w

    // softmax + lin_den per row; a overwrites scores in place, den -> sKT[0:64]
    size_t zb = (size_t)(bh * NB + n) * F2;
    float z0 = g_dZ[zb + lane], z1 = g_dZ[zb + 32 + lane];
    float z2 = g_dZ[zb + 64 + lane], z3 = g_dZ[zb + 96 + lane];
#pragma unroll
    for (int r = 0; r < 8; r++) {
        int s = warp * 8 + r;
        float sc0 = sQ[s * 64 + lane], sc1 = sQ[s * 64 + 32 + lane];
        float m = wmax(fmaxf(sc0, sc1));
        float a0 = __expf(sc0 - m), a1 = __expf(sc1 - m);
        float asum = fmaxf(wsum(a0 + a1), EPSV);
        float ld = sPhi[s * 128 + lane] * z0 + sPhi[s * 128 + 32 + lane] * z1 +
                   sPhi[s * 128 + 64 + lane] * z2 + sPhi[s * 128 + 96 + lane] * z3;
        ld = fmaxf(wsum(ld), EPSV);
        float den = fmaxf(wgt * asum + ld, EPSV);
        sQ[s * 64 + lane] = a0;
        sQ[s * 64 + 32 + lane] = a1;
        if (lane == 0) sKT[s] = den;
    }
    __syncthreads();

    // GEMM2: out = (w * (a @ v) + phi_q @ S) / den
    float lacc[4][4] = {}, smacc[4][4] = {};
    mm4x4<128, 128, 64>(sPhi, sSt, lacc, s0, c0);
    mm4x4<64, 64, 64>(sQ, sV, smacc, s0, c0);
#pragma unroll
    for (int i = 0; i < 4; i++) {
        float rden = 1.f / sKT[s0 + i];
        float4 o;
        o.x = (wgt * smacc[i][0] + lacc[i][0]) * rden;
        o.y = (wgt * smacc[i][1] + lacc[i][1]) * rden;
        o.z = (wgt * smacc[i][2] + lacc[i][2]) * rden;
        o.w = (wgt * smacc[i][3] + lacc[i][3]) * rden;
        *(float4*)&out[xb + (size_t)(s0 + i) * 64 + c0] = o;
    }
}

extern "C" void kernel_launch(void* const* d_in, const int* in_sizes, int n_in,
                              void* d_out, int out_size) {
    const float* Q = (const float*)d_in[0];
    const float* K = (const float*)d_in[1];
    const float* V = (const float*)d_in[2];
    const float* W = (const float*)d_in[3];
    const float* A = (const float*)d_in[4];
    float* out = (float*)d_out;

    cudaFuncSetAttribute(phase1_kernel, cudaFuncAttributeMaxDynamicSharedMemorySize, 98304);
    cudaFuncSetAttribute(phase2_kernel, cudaFuncAttributeMaxDynamicSharedMemorySize, 114688);

    phase1_kernel<<<BH * NB, 256, 98304>>>(K, V, W);
    scanS_kernel<<<dim3(32, BH), 256>>>();
    scanZ_kernel<<<BH, 128>>>();
    phase2_kernel<<<BH * NB, 256, 114688>>>(Q, K, V, W, A, out);
}

// round 4
// speedup vs baseline: 1.3895x; 1.1391x over previous
#include <cuda_runtime.h>

#define NB   64
#define F2   128
#define HH   16
#define LL   4096
#define BH   32
#define EPSV 1e-6f

__device__ float g_dS[(size_t)BH * NB * F2 * 64];  // 67 MB scratch
__device__ float g_dZ[(size_t)BH * NB * F2];       // 1 MB

// reductions over a 16-lane half-warp group (rows live in one group)
__device__ __forceinline__ float gmax16(float x) {
#pragma unroll
    for (int o = 1; o < 16; o <<= 1) x = fmaxf(x, __shfl_xor_sync(0xffffffffu, x, o));
    return x;
}
__device__ __forceinline__ float gsum16(float x) {
#pragma unroll
    for (int o = 1; o < 16; o <<= 1) x += __shfl_xor_sync(0xffffffffu, x, o);
    return x;
}

// acc[i][j] += sum_k A[(r0+i)*LDA+k] * B[k*LDB+c0+j]
template<int KDIM, int LDA, int LDB>
__device__ __forceinline__ void mm4x4(const float* __restrict__ A, const float* __restrict__ B,
                                      float (&acc)[4][4], int r0, int c0) {
#pragma unroll
    for (int k0 = 0; k0 < KDIM; k0 += 4) {
        float4 av[4], bv[4];
#pragma unroll
        for (int i = 0; i < 4; i++) av[i] = *(const float4*)&A[(r0 + i) * LDA + k0];
#pragma unroll
        for (int j = 0; j < 4; j++) bv[j] = *(const float4*)&B[(k0 + j) * LDB + c0];
#pragma unroll
        for (int i = 0; i < 4; i++) {
            acc[i][0] += av[i].x * bv[0].x + av[i].y * bv[1].x + av[i].z * bv[2].x + av[i].w * bv[3].x;
            acc[i][1] += av[i].x * bv[0].y + av[i].y * bv[1].y + av[i].z * bv[2].y + av[i].w * bv[3].y;
            acc[i][2] += av[i].x * bv[0].z + av[i].y * bv[1].z + av[i].z * bv[2].z + av[i].w * bv[3].z;
            acc[i][3] += av[i].x * bv[0].w + av[i].y * bv[1].w + av[i].z * bv[2].w + av[i].w * bv[3].w;
        }
    }
}

// B column-XOR-swizzled: B[k][c] at k*64 + (c ^ ((k&7)<<2))
__device__ __forceinline__ void mm4x4_kswz(const float* __restrict__ A, const float* __restrict__ B,
                                           float (&acc)[4][4], int r0, int c0) {
#pragma unroll
    for (int k0 = 0; k0 < 64; k0 += 4) {
        float4 av[4], bv[4];
#pragma unroll
        for (int i = 0; i < 4; i++) av[i] = *(const float4*)&A[(r0 + i) * 64 + k0];
#pragma unroll
        for (int j = 0; j < 4; j++)
            bv[j] = *(const float4*)&B[(k0 + j) * 64 + (c0 ^ (((k0 + j) & 7) << 2))];
#pragma unroll
        for (int i = 0; i < 4; i++) {
            acc[i][0] += av[i].x * bv[0].x + av[i].y * bv[1].x + av[i].z * bv[2].x + av[i].w * bv[3].x;
            acc[i][1] += av[i].x * bv[0].y + av[i].y * bv[1].y + av[i].z * bv[2].y + av[i].w * bv[3].y;
            acc[i][2] += av[i].x * bv[0].z + av[i].y * bv[1].z + av[i].z * bv[2].z + av[i].w * bv[3].z;
            acc[i][3] += av[i].x * bv[0].w + av[i].y * bv[1].w + av[i].z * bv[2].w + av[i].w * bv[3].w;
        }
    }
}

// phi = [softmax(u), softmax(-u)] from the register u-tile; writes sPhi.
// If LD: also ld[i] = full-row dot(phi[s0+i,:], Z[:]) (replicated across the group).
template<bool LD>
__device__ __forceinline__ void phi_regs(const float (&u)[4][4], float* __restrict__ sPhi,
                                         int s0, int f0, const float* __restrict__ Z,
                                         float (&ld)[4]) {
    float zp[4], zn[4];
    if (LD) {
#pragma unroll
        for (int j = 0; j < 4; j++) { zp[j] = Z[f0 + j]; zn[j] = Z[64 + f0 + j]; }
    }
#pragma unroll
    for (int i = 0; i < 4; i++) {
        float hi = fmaxf(fmaxf(u[i][0], u[i][1]), fmaxf(u[i][2], u[i][3]));
        float lo = fminf(fminf(u[i][0], u[i][1]), fminf(u[i][2], u[i][3]));
        hi = gmax16(hi);
        lo = -gmax16(-lo);
        float e[4], g[4], sp = 0.f, sn = 0.f;
#pragma unroll
        for (int j = 0; j < 4; j++) {
            e[j] = __expf(u[i][j] - hi);
            g[j] = __expf(lo - u[i][j]);
            sp += e[j];
            sn += g[j];
        }
        sp = gsum16(sp);
        sn = gsum16(sn);
        float rp = 1.f / sp, rn = 1.f / sn;
        float4 P = make_float4(e[0] * rp, e[1] * rp, e[2] * rp, e[3] * rp);
        float4 Nn = make_float4(g[0] * rn, g[1] * rn, g[2] * rn, g[3] * rn);
        *(float4*)&sPhi[(s0 + i) * 128 + f0] = P;
        *(float4*)&sPhi[(s0 + i) * 128 + 64 + f0] = Nn;
        if (LD) {
            float l = P.x * zp[0] + P.y * zp[1] + P.z * zp[2] + P.w * zp[3] +
                      Nn.x * zn[0] + Nn.y * zn[1] + Nn.z * zn[2] + Nn.w * zn[3];
            ld[i] = gsum16(l);
        }
    }
}

// ---------------- Phase 1: dS = phi_k^T v, dZ = colsum phi_k ---------------------
__global__ void __launch_bounds__(256, 3)
phase1_kernel(const float* __restrict__ K, const float* __restrict__ V,
              const float* __restrict__ W) {
    extern __shared__ float smem[];
    float* sK   = smem;         // 4096: k, then v
    float* sW   = sK + 4096;    // 4096
    float* sPhi = sW + 4096;    // 8192   -> 64 KB

    int t = threadIdx.x;
    int bid = blockIdx.x, bh = bid >> 6, n = bid & 63, h = bh & (HH - 1);
    size_t xb = ((size_t)bh * LL + (size_t)n * 64) * 64;

    for (int i = t; i < 4096; i += 256) {
        sK[i] = K[xb + i];
        sW[i] = W[h * 4096 + i];
    }
    __syncthreads();

    int s0 = (t >> 4) * 4, f0 = (t & 15) * 4;
    float u[4][4] = {};
    mm4x4<64, 64, 64>(sK, sW, u, s0, f0);
    float lddum[4];
    phi_regs<false>(u, sPhi, s0, f0, nullptr, lddum);
    __syncthreads();                       // u reads done, phi visible

    for (int i = t; i < 4096; i += 256) sK[i] = V[xb + i];   // v overlays k
    __syncthreads();

    // dS[f][d] = sum_s phi[s][f] * v[s][d]   (8x4 tile per thread)
    int ff = (t >> 4) * 8, d0 = (t & 15) * 4;
    float acc[8][4] = {};
#pragma unroll 4
    for (int s = 0; s < 64; s++) {
        float4 vv = *(const float4*)&sK[s * 64 + d0];
        float4 p0 = *(const float4*)&sPhi[s * 128 + ff];
        float4 p1 = *(const float4*)&sPhi[s * 128 + ff + 4];
        float p[8] = {p0.x, p0.y, p0.z, p0.w, p1.x, p1.y, p1.z, p1.w};
#pragma unroll
        for (int i = 0; i < 8; i++) {
            acc[i][0] += p[i] * vv.x;
            acc[i][1] += p[i] * vv.y;
            acc[i][2] += p[i] * vv.z;
            acc[i][3] += p[i] * vv.w;
        }
    }
    size_t sb = (size_t)(bh * NB + n) * F2 * 64;
#pragma unroll
    for (int i = 0; i < 8; i++)
        *(float4*)&g_dS[sb + (size_t)(ff + i) * 64 + d0] =
            make_float4(acc[i][0], acc[i][1], acc[i][2], acc[i][3]);
    if (t < 128) {
        float z = 0.f;
#pragma unroll 8
        for (int s = 0; s < 64; s++) z += sPhi[s * 128 + t];
        g_dZ[(size_t)(bh * NB + n) * F2 + t] = z;
    }
}

// ---------------- Exclusive prefix scans over n (in-place) -----------------------
__global__ void scanS_kernel() {
    int bh = blockIdx.y;
    int e = blockIdx.x * 256 + threadIdx.x;   // float4 index 0..2047
    float4* p = (float4*)g_dS;
    size_t base = (size_t)bh * NB * 2048 + e;
    float4 run = make_float4(0.f, 0.f, 0.f, 0.f);
#pragma unroll 8
    for (int n = 0; n < NB; n++) {
        float4 x = p[base + (size_t)n * 2048];
        p[base + (size_t)n * 2048] = run;
        run.x += x.x; run.y += x.y; run.z += x.z; run.w += x.w;
    }
}

__global__ void scanZ_kernel() {
    int bh = blockIdx.x;
    int f = threadIdx.x;
    size_t base = (size_t)bh * NB * F2 + f;
    float run = 0.f;
#pragma unroll 8
    for (int n = 0; n < NB; n++) {
        float x = g_dZ[base + (size_t)n * F2];
        g_dZ[base + (size_t)n * F2] = run;
        run += x;
    }
}

// ---------------- Phase 2: outputs -----------------------------------------------
__global__ void __launch_bounds__(256, 3)
phase2_kernel(const float* __restrict__ Q, const float* __restrict__ K,
              const float* __restrict__ V, const float* __restrict__ W,
              const float* __restrict__ alpha, float* __restrict__ out) {
    extern __shared__ float smem[];
    float* sQ   = smem;          // 4096: q, then a
    float* sB   = sQ + 4096;     // 4096: W -> kT -> V
    float* sPhi = sB + 4096;     // 8192
    float* sS   = sPhi + 8192;   // 2048: S chunk staging
    float* sDen = sS + 2048;     // 64       -> 73984 B total

    int t = threadIdx.x;
    int bid = blockIdx.x, bh = bid >> 6, n = bid & 63, h = bh & (HH - 1);
    size_t xb = ((size_t)bh * LL + (size_t)n * 64) * 64;

    for (int i = t; i < 4096; i += 256) {
        sQ[i] = Q[xb + i];
        sB[i] = W[h * 4096 + i];
    }
    __syncthreads();

    int s0 = (t >> 4) * 4, c0 = (t & 15) * 4;
    float u[4][4] = {};
    mm4x4<64, 64, 64>(sQ, sB, u, s0, c0);
    float ld[4];
    size_t zb = (size_t)(bh * NB + n) * F2;
    phi_regs<true>(u, sPhi, s0, c0, &g_dZ[zb], ld);
    __syncthreads();                      // W reads done, phi visible

    for (int i = t; i < 4096; i += 256) { // kT overlays W, XOR-swizzled columns
        int s = i >> 6, d = i & 63;
        sB[d * 64 + (s ^ ((d & 7) << 2))] = K[xb + i];
    }
    __syncthreads();

    float sc[4][4] = {};
    mm4x4_kswz(sQ, sB, sc, s0, c0);
    float wgt = 1.f / (1.f + __expf(-alpha[h]));

    // register softmax of scores + denominator
    float a[4][4], den4[4];
#pragma unroll
    for (int i = 0; i < 4; i++) {
#pragma unroll
        for (int j = 0; j < 4; j++) sc[i][j] *= 0.125f;
        float m = fmaxf(fmaxf(sc[i][0], sc[i][1]), fmaxf(sc[i][2], sc[i][3]));
        m = gmax16(m);
        float asum = 0.f;
#pragma unroll
        for (int j = 0; j < 4; j++) { a[i][j] = __expf(sc[i][j] - m); asum += a[i][j]; }
        asum = gsum16(asum);
        den4[i] = fmaxf(wgt * fmaxf(asum, EPSV) + fmaxf(ld[i], EPSV), EPSV);
    }
    {
        int lj = t & 15;
        if (lj < 4) sDen[s0 + lj] = den4[lj];
    }
    __syncwarp();     // group's own q-row reads complete before overwrite
#pragma unroll
    for (int i = 0; i < 4; i++)
        *(float4*)&sQ[(s0 + i) * 64 + c0] = make_float4(a[i][0], a[i][1], a[i][2], a[i][3]);
    __syncthreads();  // kT reads done everywhere; a + den visible

    for (int i = t; i < 4096; i += 256) sB[i] = V[xb + i];   // V overlays kT
    __syncthreads();

    float sm[4][4] = {}, lin[4][4] = {};
    mm4x4<64, 64, 64>(sQ, sB, sm, s0, c0);   // a @ v

    // lin = phi_q @ S, S streamed from L2 in 32-row chunks
    size_t sb = (size_t)(bh * NB + n) * F2 * 64;
#pragma unroll 1
    for (int c = 0; c < 4; c++) {
        for (int i = t; i < 2048; i += 256) sS[i] = g_dS[sb + (size_t)c * 2048 + i];
        __syncthreads();
#pragma unroll
        for (int k0 = 0; k0 < 32; k0 += 4) {
            float4 av[4], bv[4];
#pragma unroll
            for (int i = 0; i < 4; i++)
                av[i] = *(const float4*)&sPhi[(s0 + i) * 128 + c * 32 + k0];
#pragma unroll
            for (int j = 0; j < 4; j++) bv[j] = *(const float4*)&sS[(k0 + j) * 64 + c0];
#pragma unroll
            for (int i = 0; i < 4; i++) {
                lin[i][0] += av[i].x * bv[0].x + av[i].y * bv[1].x + av[i].z * bv[2].x + av[i].w * bv[3].x;
                lin[i][1] += av[i].x * bv[0].y + av[i].y * bv[1].y + av[i].z * bv[2].y + av[i].w * bv[3].y;
                lin[i][2] += av[i].x * bv[0].z + av[i].y * bv[1].z + av[i].z * bv[2].z + av[i].w * bv[3].z;
                lin[i][3] += av[i].x * bv[0].w + av[i].y * bv[1].w + av[i].z * bv[2].w + av[i].w * bv[3].w;
            }
        }
        __syncthreads();
    }

#pragma unroll
    for (int i = 0; i < 4; i++) {
        float rden = 1.f / sDen[s0 + i];
        float4 o;
        o.x = (wgt * sm[i][0] + lin[i][0]) * rden;
        o.y = (wgt * sm[i][1] + lin[i][1]) * rden;
        o.z = (wgt * sm[i][2] + lin[i][2]) * rden;
        o.w = (wgt * sm[i][3] + lin[i][3]) * rden;
        *(float4*)&out[xb + (size_t)(s0 + i) * 64 + c0] = o;
    }
}

extern "C" void kernel_launch(void* const* d_in, const int* in_sizes, int n_in,
                              void* d_out, int out_size) {
    const float* Q = (const float*)d_in[0];
    const float* K = (const float*)d_in[1];
    const float* V = (const float*)d_in[2];
    const float* W = (const float*)d_in[3];
    const float* A = (const float*)d_in[4];
    float* out = (float*)d_out;

    cudaFuncSetAttribute(phase1_kernel, cudaFuncAttributeMaxDynamicSharedMemorySize, 65536);
    cudaFuncSetAttribute(phase2_kernel, cudaFuncAttributeMaxDynamicSharedMemorySize, 73984);

    phase1_kernel<<<BH * NB, 256, 65536>>>(K, V, W);
    scanS_kernel<<<dim3(8, BH), 256>>>();
    scanZ_kernel<<<BH, 128>>>();
    phase2_kernel<<<BH * NB, 256, 73984>>>(Q, K, V, W, A, out);
}

// round 5
// speedup vs baseline: 1.3931x; 1.0026x over previous
#include <cuda_runtime.h>

#define NB   64
#define F2   128
#define HH   16
#define LL   4096
#define BH   32
#define EPSV 1e-6f

__device__ float g_dS[(size_t)BH * NB * F2 * 64];  // 67 MB scratch
__device__ float g_dZ[(size_t)BH * NB * F2];       // 1 MB

// reductions over a 16-lane half-warp group (rows live in one group)
__device__ __forceinline__ float gmax16(float x) {
#pragma unroll
    for (int o = 1; o < 16; o <<= 1) x = fmaxf(x, __shfl_xor_sync(0xffffffffu, x, o));
    return x;
}
__device__ __forceinline__ float gsum16(float x) {
#pragma unroll
    for (int o = 1; o < 16; o <<= 1) x += __shfl_xor_sync(0xffffffffu, x, o);
    return x;
}

// acc[i][j] += sum_k A[(r0+i)*LDA+k] * B[k*LDB+c0+j]
template<int KDIM, int LDA, int LDB>
__device__ __forceinline__ void mm4x4(const float* __restrict__ A, const float* __restrict__ B,
                                      float (&acc)[4][4], int r0, int c0) {
#pragma unroll
    for (int k0 = 0; k0 < KDIM; k0 += 4) {
        float4 av[4], bv[4];
#pragma unroll
        for (int i = 0; i < 4; i++) av[i] = *(const float4*)&A[(r0 + i) * LDA + k0];
#pragma unroll
        for (int j = 0; j < 4; j++) bv[j] = *(const float4*)&B[(k0 + j) * LDB + c0];
#pragma unroll
        for (int i = 0; i < 4; i++) {
            acc[i][0] += av[i].x * bv[0].x + av[i].y * bv[1].x + av[i].z * bv[2].x + av[i].w * bv[3].x;
            acc[i][1] += av[i].x * bv[0].y + av[i].y * bv[1].y + av[i].z * bv[2].y + av[i].w * bv[3].y;
            acc[i][2] += av[i].x * bv[0].z + av[i].y * bv[1].z + av[i].z * bv[2].z + av[i].w * bv[3].z;
            acc[i][3] += av[i].x * bv[0].w + av[i].y * bv[1].w + av[i].z * bv[2].w + av[i].w * bv[3].w;
        }
    }
}

// B column-XOR-swizzled: B[k][c] at k*64 + (c ^ ((k&7)<<2))
__device__ __forceinline__ void mm4x4_kswz(const float* __restrict__ A, const float* __restrict__ B,
                                           float (&acc)[4][4], int r0, int c0) {
#pragma unroll
    for (int k0 = 0; k0 < 64; k0 += 4) {
        float4 av[4], bv[4];
#pragma unroll
        for (int i = 0; i < 4; i++) av[i] = *(const float4*)&A[(r0 + i) * 64 + k0];
#pragma unroll
        for (int j = 0; j < 4; j++)
            bv[j] = *(const float4*)&B[(k0 + j) * 64 + (c0 ^ (((k0 + j) & 7) << 2))];
#pragma unroll
        for (int i = 0; i < 4; i++) {
            acc[i][0] += av[i].x * bv[0].x + av[i].y * bv[1].x + av[i].z * bv[2].x + av[i].w * bv[3].x;
            acc[i][1] += av[i].x * bv[0].y + av[i].y * bv[1].y + av[i].z * bv[2].y + av[i].w * bv[3].y;
            acc[i][2] += av[i].x * bv[0].z + av[i].y * bv[1].z + av[i].z * bv[2].z + av[i].w * bv[3].z;
            acc[i][3] += av[i].x * bv[0].w + av[i].y * bv[1].w + av[i].z * bv[2].w + av[i].w * bv[3].w;
        }
    }
}

// phi = [softmax(u), softmax(-u)] from the register u-tile; writes sPhi.
// If LD: also ld[i] = full-row dot(phi[s0+i,:], Z[:]) (replicated across the group).
template<bool LD>
__device__ __forceinline__ void phi_regs(const float (&u)[4][4], float* __restrict__ sPhi,
                                         int s0, int f0, const float* __restrict__ Z,
                                         float (&ld)[4]) {
    float zp[4], zn[4];
    if (LD) {
#pragma unroll
        for (int j = 0; j < 4; j++) { zp[j] = Z[f0 + j]; zn[j] = Z[64 + f0 + j]; }
    }
#pragma unroll
    for (int i = 0; i < 4; i++) {
        float hi = fmaxf(fmaxf(u[i][0], u[i][1]), fmaxf(u[i][2], u[i][3]));
        float lo = fminf(fminf(u[i][0], u[i][1]), fminf(u[i][2], u[i][3]));
        hi = gmax16(hi);
        lo = -gmax16(-lo);
        float e[4], g[4], sp = 0.f, sn = 0.f;
#pragma unroll
        for (int j = 0; j < 4; j++) {
            e[j] = __expf(u[i][j] - hi);
            g[j] = __expf(lo - u[i][j]);
            sp += e[j];
            sn += g[j];
        }
        sp = gsum16(sp);
        sn = gsum16(sn);
        float rp = 1.f / sp, rn = 1.f / sn;
        float4 P = make_float4(e[0] * rp, e[1] * rp, e[2] * rp, e[3] * rp);
        float4 Nn = make_float4(g[0] * rn, g[1] * rn, g[2] * rn, g[3] * rn);
        *(float4*)&sPhi[(s0 + i) * 128 + f0] = P;
        *(float4*)&sPhi[(s0 + i) * 128 + 64 + f0] = Nn;
        if (LD) {
            float l = P.x * zp[0] + P.y * zp[1] + P.z * zp[2] + P.w * zp[3] +
                      Nn.x * zn[0] + Nn.y * zn[1] + Nn.z * zn[2] + Nn.w * zn[3];
            ld[i] = gsum16(l);
        }
    }
}

// ---------------- Phase 1: dS = phi_k^T v, dZ = colsum phi_k ---------------------
__global__ void __launch_bounds__(256, 3)
phase1_kernel(const float* __restrict__ K, const float* __restrict__ V,
              const float* __restrict__ W) {
    extern __shared__ float smem[];
    float* sK   = smem;         // 4096: k, then v
    float* sW   = sK + 4096;    // 4096
    float* sPhi = sW + 4096;    // 8192   -> 64 KB

    int t = threadIdx.x;
    int bid = blockIdx.x, bh = bid >> 6, n = bid & 63, h = bh & (HH - 1);
    size_t xb = ((size_t)bh * LL + (size_t)n * 64) * 64;

    for (int i = t; i < 4096; i += 256) {
        sK[i] = K[xb + i];
        sW[i] = W[h * 4096 + i];
    }
    __syncthreads();

    int s0 = (t >> 4) * 4, f0 = (t & 15) * 4;
    float u[4][4] = {};
    mm4x4<64, 64, 64>(sK, sW, u, s0, f0);
    float lddum[4];
    phi_regs<false>(u, sPhi, s0, f0, nullptr, lddum);
    __syncthreads();                       // u reads done, phi visible

    for (int i = t; i < 4096; i += 256) sK[i] = V[xb + i];   // v overlays k
    __syncthreads();

    // dS[f][d] = sum_s phi[s][f] * v[s][d]   (8x4 tile per thread)
    int ff = (t >> 4) * 8, d0 = (t & 15) * 4;
    float acc[8][4] = {};
#pragma unroll 4
    for (int s = 0; s < 64; s++) {
        float4 vv = *(const float4*)&sK[s * 64 + d0];
        float4 p0 = *(const float4*)&sPhi[s * 128 + ff];
        float4 p1 = *(const float4*)&sPhi[s * 128 + ff + 4];
        float p[8] = {p0.x, p0.y, p0.z, p0.w, p1.x, p1.y, p1.z, p1.w};
#pragma unroll
        for (int i = 0; i < 8; i++) {
            acc[i][0] += p[i] * vv.x;
            acc[i][1] += p[i] * vv.y;
            acc[i][2] += p[i] * vv.z;
            acc[i][3] += p[i] * vv.w;
        }
    }
    size_t sb = (size_t)(bh * NB + n) * F2 * 64;
#pragma unroll
    for (int i = 0; i < 8; i++)
        *(float4*)&g_dS[sb + (size_t)(ff + i) * 64 + d0] =
            make_float4(acc[i][0], acc[i][1], acc[i][2], acc[i][3]);
    if (t < 128) {
        float z = 0.f;
#pragma unroll 8
        for (int s = 0; s < 64; s++) z += sPhi[s * 128 + t];
        g_dZ[(size_t)(bh * NB + n) * F2 + t] = z;
    }
}

// ---------------- Exclusive prefix scans over n (in-place) -----------------------
__global__ void scanS_kernel() {
    int bh = blockIdx.y;
    int e = blockIdx.x * 256 + threadIdx.x;   // float4 index 0..2047
    float4* p = (float4*)g_dS;
    size_t base = (size_t)bh * NB * 2048 + e;
    float4 run = make_float4(0.f, 0.f, 0.f, 0.f);
#pragma unroll 8
    for (int n = 0; n < NB; n++) {
        float4 x = p[base + (size_t)n * 2048];
        p[base + (size_t)n * 2048] = run;
        run.x += x.x; run.y += x.y; run.z += x.z; run.w += x.w;
    }
}

__global__ void scanZ_kernel() {
    int bh = blockIdx.x;
    int f = threadIdx.x;
    size_t base = (size_t)bh * NB * F2 + f;
    float run = 0.f;
#pragma unroll 8
    for (int n = 0; n < NB; n++) {
        float x = g_dZ[base + (size_t)n * F2];
        g_dZ[base + (size_t)n * F2] = run;
        run += x;
    }
}

// ---------------- Phase 2: outputs -----------------------------------------------
__global__ void __launch_bounds__(256, 3)
phase2_kernel(const float* __restrict__ Q, const float* __restrict__ K,
              const float* __restrict__ V, const float* __restrict__ W,
              const float* __restrict__ alpha, float* __restrict__ out) {
    extern __shared__ float smem[];
    float* sQ   = smem;          // 4096: q, then a
    float* sB   = sQ + 4096;     // 4096: W -> kT -> V
    float* sPhi = sB + 4096;     // 8192
    float* sS   = sPhi + 8192;   // 2048: S chunk staging
    float* sDen = sS + 2048;     // 64       -> 73984 B total

    int t = threadIdx.x;
    int bid = blockIdx.x, bh = bid >> 6, n = bid & 63, h = bh & (HH - 1);
    size_t xb = ((size_t)bh * LL + (size_t)n * 64) * 64;

    for (int i = t; i < 4096; i += 256) {
        sQ[i] = Q[xb + i];
        sB[i] = W[h * 4096 + i];
    }
    __syncthreads();

    int s0 = (t >> 4) * 4, c0 = (t & 15) * 4;
    float u[4][4] = {};
    mm4x4<64, 64, 64>(sQ, sB, u, s0, c0);
    float ld[4];
    size_t zb = (size_t)(bh * NB + n) * F2;
    phi_regs<true>(u, sPhi, s0, c0, &g_dZ[zb], ld);
    __syncthreads();                      // W reads done, phi visible

    for (int i = t; i < 4096; i += 256) { // kT overlays W, XOR-swizzled columns
        int s = i >> 6, d = i & 63;
        sB[d * 64 + (s ^ ((d & 7) << 2))] = K[xb + i];
    }
    __syncthreads();

    float sc[4][4] = {};
    mm4x4_kswz(sQ, sB, sc, s0, c0);
    float wgt = 1.f / (1.f + __expf(-alpha[h]));

    // register softmax of scores + denominator
    float a[4][4], den4[4];
#pragma unroll
    for (int i = 0; i < 4; i++) {
#pragma unroll
        for (int j = 0; j < 4; j++) sc[i][j] *= 0.125f;
        float m = fmaxf(fmaxf(sc[i][0], sc[i][1]), fmaxf(sc[i][2], sc[i][3]));
        m = gmax16(m);
        float asum = 0.f;
#pragma unroll
        for (int j = 0; j < 4; j++) { a[i][j] = __expf(sc[i][j] - m); asum += a[i][j]; }
        asum = gsum16(asum);
        den4[i] = fmaxf(wgt * fmaxf(asum, EPSV) + fmaxf(ld[i], EPSV), EPSV);
    }
    {
        int lj = t & 15;
        if (lj < 4) sDen[s0 + lj] = den4[lj];
    }
    __syncwarp();     // group's own q-row reads complete before overwrite
#pragma unroll
    for (int i = 0; i < 4; i++)
        *(float4*)&sQ[(s0 + i) * 64 + c0] = make_float4(a[i][0], a[i][1], a[i][2], a[i][3]);
    __syncthreads();  // kT reads done everywhere; a + den visible

    for (int i = t; i < 4096; i += 256) sB[i] = V[xb + i];   // V overlays kT
    __syncthreads();

    float sm[4][4] = {}, lin[4][4] = {};
    mm4x4<64, 64, 64>(sQ, sB, sm, s0, c0);   // a @ v

    // lin = phi_q @ S, S streamed from L2 in 32-row chunks
    size_t sb = (size_t)(bh * NB + n) * F2 * 64;
#pragma unroll 1
    for (int c = 0; c < 4; c++) {
        for (int i = t; i < 2048; i += 256) sS[i] = g_dS[sb + (size_t)c * 2048 + i];
        __syncthreads();
#pragma unroll
        for (int k0 = 0; k0 < 32; k0 += 4) {
            float4 av[4], bv[4];
#pragma unroll
            for (int i = 0; i < 4; i++)
                av[i] = *(const float4*)&sPhi[(s0 + i) * 128 + c * 32 + k0];
#pragma unroll
            for (int j = 0; j < 4; j++) bv[j] = *(const float4*)&sS[(k0 + j) * 64 + c0];
#pragma unroll
            for (int i = 0; i < 4; i++) {
                lin[i][0] += av[i].x * bv[0].x + av[i].y * bv[1].x + av[i].z * bv[2].x + av[i].w * bv[3].x;
                lin[i][1] += av[i].x * bv[0].y + av[i].y * bv[1].y + av[i].z * bv[2].y + av[i].w * bv[3].y;
                lin[i][2] += av[i].x * bv[0].z + av[i].y * bv[1].z + av[i].z * bv[2].z + av[i].w * bv[3].z;
                lin[i][3] += av[i].x * bv[0].w + av[i].y * bv[1].w + av[i].z * bv[2].w + av[i].w * bv[3].w;
            }
        }
        __syncthreads();
    }

#pragma unroll
    for (int i = 0; i < 4; i++) {
        float rden = 1.f / sDen[s0 + i];
        float4 o;
        o.x = (wgt * sm[i][0] + lin[i][0]) * rden;
        o.y = (wgt * sm[i][1] + lin[i][1]) * rden;
        o.z = (wgt * sm[i][2] + lin[i][2]) * rden;
        o.w = (wgt * sm[i][3] + lin[i][3]) * rden;
        *(float4*)&out[xb + (size_t)(s0 + i) * 64 + c0] = o;
    }
}

extern "C" void kernel_launch(void* const* d_in, const int* in_sizes, int n_in,
                              void* d_out, int out_size) {
    const float* Q = (const float*)d_in[0];
    const float* K = (const float*)d_in[1];
    const float* V = (const float*)d_in[2];
    const float* W = (const float*)d_in[3];
    const float* A = (const float*)d_in[4];
    float* out = (float*)d_out;

    cudaFuncSetAttribute(phase1_kernel, cudaFuncAttributeMaxDynamicSharedMemorySize, 65536);
    cudaFuncSetAttribute(phase2_kernel, cudaFuncAttributeMaxDynamicSharedMemorySize, 73984);

    phase1_kernel<<<BH * NB, 256, 65536>>>(K, V, W);
    scanS_kernel<<<dim3(8, BH), 256>>>();
    scanZ_kernel<<<BH, 128>>>();
    phase2_kernel<<<BH * NB, 256, 73984>>>(Q, K, V, W, A, out);
}

// round 7
// speedup vs baseline: 1.6728x; 1.2008x over previous
#include <cuda_runtime.h>

#define NB 64
#define F2 128
#define HH 16
#define LL 4096
#define BH 32
#define EPSV 1e-6f

__device__ float g_dS[(size_t)BH * NB * F2 * 64];  // 67 MB scratch
__device__ float g_dZ[(size_t)BH * NB * F2];       // 1 MB

__device__ __forceinline__ float tf32r(float x) {
    unsigned r;
    asm("cvt.rna.tf32.f32 %0, %1;" : "=r"(r) : "f"(x));
    return __uint_as_float(r);
}

__device__ __forceinline__ void mma8(float* c, const float* a, const float* b) {
    asm volatile(
        "mma.sync.aligned.m16n8k8.row.col.f32.tf32.tf32.f32 "
        "{%0,%1,%2,%3},{%4,%5,%6,%7},{%8,%9},{%0,%1,%2,%3};"
        : "+f"(c[0]), "+f"(c[1]), "+f"(c[2]), "+f"(c[3])
        : "r"(__float_as_uint(a[0])), "r"(__float_as_uint(a[1])),
          "r"(__float_as_uint(a[2])), "r"(__float_as_uint(a[3])),
          "r"(__float_as_uint(b[0])), "r"(__float_as_uint(b[1])));
}

__device__ __forceinline__ float rmax4(float x) {
    x = fmaxf(x, __shfl_xor_sync(0xffffffffu, x, 1));
    x = fmaxf(x, __shfl_xor_sync(0xffffffffu, x, 2));
    return x;
}
__device__ __forceinline__ float rsum4(float x) {
    x += __shfl_xor_sync(0xffffffffu, x, 1);
    x += __shfl_xor_sync(0xffffffffu, x, 2);
    return x;
}

// A fragment, row-major A[m][k], stride ld
__device__ __forceinline__ void ldA(const float* S, int ld, int m0, int k0, int g, int t, float* a) {
    const float* p = S + (m0 + g) * ld + k0 + t;
    a[0] = p[0]; a[1] = p[8 * ld]; a[2] = p[4]; a[3] = p[8 * ld + 4];
}
// A fragment where A[m][k] = S[k][m] (transposed source), stride ld
__device__ __forceinline__ void ldAT(const float* S, int ld, int m0, int k0, int g, int t, float* a) {
    const float* p = S + (k0 + t) * ld + m0 + g;
    a[0] = p[0]; a[1] = p[8]; a[2] = p[4 * ld]; a[3] = p[4 * ld + 8];
}
// B fragment, B[k][n] from row-major S[k][n], stride ld
__device__ __forceinline__ void ldB(const float* S, int ld, int k0, int n0, int g, int t, float* b) {
    const float* p = S + (k0 + t) * ld + n0 + g;
    b[0] = p[0]; b[1] = p[4 * ld];
}
// B fragment, B[k][n] = S[n][k] (transposed source), stride ld
__device__ __forceinline__ void ldBT(const float* S, int ld, int k0, int n0, int g, int t, float* b) {
    const float* p = S + (n0 + g) * ld + k0 + t;
    b[0] = p[0]; b[1] = p[4];
}

// 16x32 tile (4 N-subtiles) GEMM: C += A(m0:+16, 0:KD) * B(0:KD, n0:+32)
template<int KD, int LDA, int LDB, bool BT>
__device__ __forceinline__ void wgemm(const float* A, const float* B, float (&c)[4][4],
                                      int m0, int n0, int g, int t) {
#pragma unroll
    for (int k0 = 0; k0 < KD; k0 += 8) {
        float a[4];
        ldA(A, LDA, m0, k0, g, t, a);
#pragma unroll
        for (int nt = 0; nt < 4; nt++) {
            float b[2];
            if (BT) ldBT(B, LDB, k0, n0 + 8 * nt, g, t, b);
            else    ldB(B, LDB, k0, n0 + 8 * nt, g, t, b);
            mma8(c[nt], a, b);
        }
    }
}

// ======================= Phase 1: dS = phi_k^T v, dZ = colsum phi_k ==============
__global__ void __launch_bounds__(256, 3)
phase1_kernel(const float* __restrict__ K, const float* __restrict__ V,
              const float* __restrict__ W) {
    extern __shared__ float smem[];
    float* sK   = smem;             // 64*68: k (tf32)
    float* sB   = sK + 64 * 68;     // 64*72: W then v (tf32)
    float* sPhi = sB + 64 * 72;     // 64*132
    float* R0   = sPhi + 64 * 132;  // 128 (hi)
    float* R1   = R0 + 128;         // 128 (lo)
    float* R2   = R1 + 128;         // 128 (sum+)
    float* R3   = R2 + 128;         // 128 (sum-)   -> 17920 floats = 71680 B

    int t = threadIdx.x, w = t >> 5, lane = t & 31, g = lane >> 2, tg = lane & 3;
    int mt = w >> 1, nh = w & 1, m0 = mt * 16, n0 = nh * 32;
    int bid = blockIdx.x, bh = bid >> 6, n = bid & 63, h = bh & (HH - 1);
    size_t xb = ((size_t)bh * LL + (size_t)n * 64) * 64;

    for (int i = t; i < 4096; i += 256) {
        int r = i >> 6, cc = i & 63;
        sK[r * 68 + cc] = tf32r(K[xb + i]);
        sB[r * 72 + cc] = tf32r(W[h * 4096 + i]);
    }
    __syncthreads();  // B0

    int r0 = m0 + g, r1 = r0 + 8;
    float u[4][4] = {};
    wgemm<64, 68, 72, false>(sK, sB, u, m0, n0, g, tg);

    float hi0 = -3e38f, lo0 = 3e38f, hi1 = -3e38f, lo1 = 3e38f;
#pragma unroll
    for (int nt = 0; nt < 4; nt++) {
        hi0 = fmaxf(hi0, fmaxf(u[nt][0], u[nt][1]));
        lo0 = fminf(lo0, fminf(u[nt][0], u[nt][1]));
        hi1 = fmaxf(hi1, fmaxf(u[nt][2], u[nt][3]));
        lo1 = fminf(lo1, fminf(u[nt][2], u[nt][3]));
    }
    hi0 = rmax4(hi0); lo0 = -rmax4(-lo0); hi1 = rmax4(hi1); lo1 = -rmax4(-lo1);
    if (tg == 0) {
        R0[r0 * 2 + nh] = hi0; R0[r1 * 2 + nh] = hi1;
        R1[r0 * 2 + nh] = lo0; R1[r1 * 2 + nh] = lo1;
    }
    __syncthreads();  // B1
    hi0 = fmaxf(R0[r0 * 2], R0[r0 * 2 + 1]); hi1 = fmaxf(R0[r1 * 2], R0[r1 * 2 + 1]);
    lo0 = fminf(R1[r0 * 2], R1[r0 * 2 + 1]); lo1 = fminf(R1[r1 * 2], R1[r1 * 2 + 1]);

    float ee[4][4], gg[4][4];
    float sp0 = 0.f, sp1 = 0.f, sn0 = 0.f, sn1 = 0.f;
#pragma unroll
    for (int nt = 0; nt < 4; nt++) {
        ee[nt][0] = __expf(u[nt][0] - hi0); ee[nt][1] = __expf(u[nt][1] - hi0);
        ee[nt][2] = __expf(u[nt][2] - hi1); ee[nt][3] = __expf(u[nt][3] - hi1);
        gg[nt][0] = __expf(lo0 - u[nt][0]); gg[nt][1] = __expf(lo0 - u[nt][1]);
        gg[nt][2] = __expf(lo1 - u[nt][2]); gg[nt][3] = __expf(lo1 - u[nt][3]);
        sp0 += ee[nt][0] + ee[nt][1]; sp1 += ee[nt][2] + ee[nt][3];
        sn0 += gg[nt][0] + gg[nt][1]; sn1 += gg[nt][2] + gg[nt][3];
    }
    sp0 = rsum4(sp0); sp1 = rsum4(sp1); sn0 = rsum4(sn0); sn1 = rsum4(sn1);
    if (tg == 0) {
        R2[r0 * 2 + nh] = sp0; R2[r1 * 2 + nh] = sp1;
        R3[r0 * 2 + nh] = sn0; R3[r1 * 2 + nh] = sn1;
    }
    for (int i = t; i < 4096; i += 256)  // v overlays W
        sB[(i >> 6) * 72 + (i & 63)] = tf32r(V[xb + i]);
    __syncthreads();  // B2
    float rp0 = 1.f / (R2[r0 * 2] + R2[r0 * 2 + 1]);
    float rp1 = 1.f / (R2[r1 * 2] + R2[r1 * 2 + 1]);
    float rn0 = 1.f / (R3[r0 * 2] + R3[r0 * 2 + 1]);
    float rn1 = 1.f / (R3[r1 * 2] + R3[r1 * 2 + 1]);
#pragma unroll
    for (int nt = 0; nt < 4; nt++) {
        int c = n0 + 8 * nt + 2 * tg;
        float2 v2;
        v2.x = tf32r(ee[nt][0] * rp0); v2.y = tf32r(ee[nt][1] * rp0);
        *(float2*)&sPhi[r0 * 132 + c] = v2;
        v2.x = tf32r(gg[nt][0] * rn0); v2.y = tf32r(gg[nt][1] * rn0);
        *(float2*)&sPhi[r0 * 132 + 64 + c] = v2;
        v2.x = tf32r(ee[nt][2] * rp1); v2.y = tf32r(ee[nt][3] * rp1);
        *(float2*)&sPhi[r1 * 132 + c] = v2;
        v2.x = tf32r(gg[nt][2] * rn1); v2.y = tf32r(gg[nt][3] * rn1);
        *(float2*)&sPhi[r1 * 132 + 64 + c] = v2;
    }
    __syncthreads();  // B3: phi ready, v ready

    // dS: warp w computes f-rows 16w..16w+15, all 64 d-cols
    int m0d = 16 * w;
    size_t sb = (size_t)(bh * NB + n) * F2 * 64;
    float acc[8][4] = {};
#pragma unroll
    for (int k0 = 0; k0 < 64; k0 += 8) {
        float a[4];
        ldAT(sPhi, 132, m0d, k0, g, tg, a);
#pragma unroll
        for (int nt = 0; nt < 8; nt++) {
            float b[2];
            ldB(sB, 72, k0, 8 * nt, g, tg, b);
            mma8(acc[nt], a, b);
        }
    }
#pragma unroll
    for (int nt = 0; nt < 8; nt++) {
        float2 o;
        o.x = acc[nt][0]; o.y = acc[nt][1];
        *(float2*)&g_dS[sb + (size_t)(m0d + g) * 64 + 8 * nt + 2 * tg] = o;
        o.x = acc[nt][2]; o.y = acc[nt][3];
        *(float2*)&g_dS[sb + (size_t)(m0d + g + 8) * 64 + 8 * nt + 2 * tg] = o;
    }
    if (t < 128) {
        float z = 0.f;
#pragma unroll 8
        for (int s = 0; s < 64; s++) z += sPhi[s * 132 + t];
        g_dZ[(size_t)(bh * NB + n) * F2 + t] = z;
    }
}

// ======================= Exclusive prefix scans over n (in-place) ================
__global__ void scanS_kernel() {
    int bh = blockIdx.y;
    int e = blockIdx.x * 256 + threadIdx.x;  // float4 index 0..2047
    float4* p = (float4*)g_dS;
    size_t base = (size_t)bh * NB * 2048 + e;
    float4 run = make_float4(0.f, 0.f, 0.f, 0.f);
#pragma unroll 8
    for (int n = 0; n < NB; n++) {
        float4 x = p[base + (size_t)n * 2048];
        p[base + (size_t)n * 2048] = run;
        run.x += x.x; run.y += x.y; run.z += x.z; run.w += x.w;
    }
}

__global__ void scanZ_kernel() {
    int bh = blockIdx.x;
    int f = threadIdx.x;
    size_t base = (size_t)bh * NB * F2 + f;
    float run = 0.f;
#pragma unroll 8
    for (int n = 0; n < NB; n++) {
        float x = g_dZ[base + (size_t)n * F2];
        g_dZ[base + (size_t)n * F2] = run;
        run += x;
    }
}

// ======================= Phase 2: outputs ========================================
__global__ void __launch_bounds__(256, 2)
phase2_kernel(const float* __restrict__ Q, const float* __restrict__ K,
              const float* __restrict__ V, const float* __restrict__ W,
              const float* __restrict__ alpha, float* __restrict__ out) {
    extern __shared__ float smem[];
    float* sQ   = smem;             // 64*68: q (tf32), later a
    float* sK   = sQ + 64 * 68;     // 64*68: k (tf32)
    float* sB   = sK + 64 * 68;     // 64*72: W then v
    float* sPhi = sB + 64 * 72;     // 64*132
    float* sS   = sPhi + 64 * 132;  // 32*72: S chunk
    float* R0   = sS + 32 * 72;     // hi / score-max
    float* R1   = R0 + 128;         // lo / asum
    float* R2   = R1 + 128;         // sum+
    float* R3   = R2 + 128;         // sum-
    float* R4   = R3 + 128;         // lin_den partials  -> 24704 floats = 98816 B

    int t = threadIdx.x, w = t >> 5, lane = t & 31, g = lane >> 2, tg = lane & 3;
    int mt = w >> 1, nh = w & 1, m0 = mt * 16, n0 = nh * 32;
    int bid = blockIdx.x, bh = bid >> 6, n = bid & 63, h = bh & (HH - 1);
    size_t xb = ((size_t)bh * LL + (size_t)n * 64) * 64;
    size_t zb = (size_t)(bh * NB + n) * F2;
    size_t sb = (size_t)(bh * NB + n) * F2 * 64;

    for (int i = t; i < 4096; i += 256) {
        int r = i >> 6, cc = i & 63;
        sQ[r * 68 + cc] = tf32r(Q[xb + i]);
        sK[r * 68 + cc] = tf32r(K[xb + i]);
        sB[r * 72 + cc] = tf32r(W[h * 4096 + i]);
    }
    __syncthreads();  // B0

    int r0 = m0 + g, r1 = r0 + 8;
    // u = q @ W
    float u[4][4] = {};
    wgemm<64, 68, 72, false>(sQ, sB, u, m0, n0, g, tg);

    float hi0 = -3e38f, lo0 = 3e38f, hi1 = -3e38f, lo1 = 3e38f;
#pragma unroll
    for (int nt = 0; nt < 4; nt++) {
        hi0 = fmaxf(hi0, fmaxf(u[nt][0], u[nt][1]));
        lo0 = fminf(lo0, fminf(u[nt][0], u[nt][1]));
        hi1 = fmaxf(hi1, fmaxf(u[nt][2], u[nt][3]));
        lo1 = fminf(lo1, fminf(u[nt][2], u[nt][3]));
    }
    hi0 = rmax4(hi0); lo0 = -rmax4(-lo0); hi1 = rmax4(hi1); lo1 = -rmax4(-lo1);
    if (tg == 0) {
        R0[r0 * 2 + nh] = hi0; R0[r1 * 2 + nh] = hi1;
        R1[r0 * 2 + nh] = lo0; R1[r1 * 2 + nh] = lo1;
    }
    __syncthreads();  // B1
    hi0 = fmaxf(R0[r0 * 2], R0[r0 * 2 + 1]); hi1 = fmaxf(R0[r1 * 2], R0[r1 * 2 + 1]);
    lo0 = fminf(R1[r0 * 2], R1[r0 * 2 + 1]); lo1 = fminf(R1[r1 * 2], R1[r1 * 2 + 1]);

    float ee[4][4], gg[4][4];
    float sp0 = 0.f, sp1 = 0.f, sn0 = 0.f, sn1 = 0.f;
#pragma unroll
    for (int nt = 0; nt < 4; nt++) {
        ee[nt][0] = __expf(u[nt][0] - hi0); ee[nt][1] = __expf(u[nt][1] - hi0);
        ee[nt][2] = __expf(u[nt][2] - hi1); ee[nt][3] = __expf(u[nt][3] - hi1);
        gg[nt][0] = __expf(lo0 - u[nt][0]); gg[nt][1] = __expf(lo0 - u[nt][1]);
        gg[nt][2] = __expf(lo1 - u[nt][2]); gg[nt][3] = __expf(lo1 - u[nt][3]);
        sp0 += ee[nt][0] + ee[nt][1]; sp1 += ee[nt][2] + ee[nt][3];
        sn0 += gg[nt][0] + gg[nt][1]; sn1 += gg[nt][2] + gg[nt][3];
    }
    sp0 = rsum4(sp0); sp1 = rsum4(sp1); sn0 = rsum4(sn0); sn1 = rsum4(sn1);
    if (tg == 0) {
        R2[r0 * 2 + nh] = sp0; R2[r1 * 2 + nh] = sp1;
        R3[r0 * 2 + nh] = sn0; R3[r1 * 2 + nh] = sn1;
    }
    for (int i = t; i < 4096; i += 256)  // v overlays W (W reads done pre-B1)
        sB[(i >> 6) * 72 + (i & 63)] = tf32r(V[xb + i]);
    __syncthreads();  // B2

    float rp0 = 1.f / (R2[r0 * 2] + R2[r0 * 2 + 1]);
    float rp1 = 1.f / (R2[r1 * 2] + R2[r1 * 2 + 1]);
    float rn0 = 1.f / (R3[r0 * 2] + R3[r0 * 2 + 1]);
    float rn1 = 1.f / (R3[r1 * 2] + R3[r1 * 2 + 1]);
    float ld0 = 0.f, ld1 = 0.f;
#pragma unroll
    for (int nt = 0; nt < 4; nt++) {
        int c = n0 + 8 * nt + 2 * tg;
        float zp0 = g_dZ[zb + c], zp1 = g_dZ[zb + c + 1];
        float zn0 = g_dZ[zb + 64 + c], zn1 = g_dZ[zb + 64 + c + 1];
        float p00 = ee[nt][0] * rp0, p01 = ee[nt][1] * rp0;
        float p10 = ee[nt][2] * rp1, p11 = ee[nt][3] * rp1;
        float q00 = gg[nt][0] * rn0, q01 = gg[nt][1] * rn0;
        float q10 = gg[nt][2] * rn1, q11 = gg[nt][3] * rn1;
        float2 v2;
        v2.x = tf32r(p00); v2.y = tf32r(p01); *(float2*)&sPhi[r0 * 132 + c] = v2;
        v2.x = tf32r(q00); v2.y = tf32r(q01); *(float2*)&sPhi[r0 * 132 + 64 + c] = v2;
        v2.x = tf32r(p10); v2.y = tf32r(p11); *(float2*)&sPhi[r1 * 132 + c] = v2;
        v2.x = tf32r(q10); v2.y = tf32r(q11); *(float2*)&sPhi[r1 * 132 + 64 + c] = v2;
        ld0 += p00 * zp0 + p01 * zp1 + q00 * zn0 + q01 * zn1;
        ld1 += p10 * zp0 + p11 * zp1 + q10 * zn0 + q11 * zn1;
    }
    ld0 = rsum4(ld0); ld1 = rsum4(ld1);
    if (tg == 0) { R4[r0 * 2 + nh] = ld0; R4[r1 * 2 + nh] = ld1; }

    // prefetch S chunk 0
    for (int i = t; i < 2048; i += 256)
        sS[(i >> 6) * 72 + (i & 63)] = tf32r(g_dS[sb + i]);

    // scores = q @ k^T (scaled)
    float sc[4][4] = {};
    wgemm<64, 68, 68, true>(sQ, sK, sc, m0, n0, g, tg);
    float mx0 = -3e38f, mx1 = -3e38f;
#pragma unroll
    for (int nt = 0; nt < 4; nt++) {
#pragma unroll
        for (int j = 0; j < 4; j++) sc[nt][j] *= 0.125f;
        mx0 = fmaxf(mx0, fmaxf(sc[nt][0], sc[nt][1]));
        mx1 = fmaxf(mx1, fmaxf(sc[nt][2], sc[nt][3]));
    }
    mx0 = rmax4(mx0); mx1 = rmax4(mx1);
    if (tg == 0) { R0[r0 * 2 + nh] = mx0; R0[r1 * 2 + nh] = mx1; }  // R0 reads done pre-B2
    __syncthreads();  // B3

    mx0 = fmaxf(R0[r0 * 2], R0[r0 * 2 + 1]); mx1 = fmaxf(R0[r1 * 2], R0[r1 * 2 + 1]);
    float as0 = 0.f, as1 = 0.f;
#pragma unroll
    for (int nt = 0; nt < 4; nt++) {
        sc[nt][0] = __expf(sc[nt][0] - mx0); sc[nt][1] = __expf(sc[nt][1] - mx0);
        sc[nt][2] = __expf(sc[nt][2] - mx1); sc[nt][3] = __expf(sc[nt][3] - mx1);
        as0 += sc[nt][0] + sc[nt][1]; as1 += sc[nt][2] + sc[nt][3];
    }
    as0 = rsum4(as0); as1 = rsum4(as1);
    if (tg == 0) { R1[r0 * 2 + nh] = as0; R1[r1 * 2 + nh] = as1; }
#pragma unroll
    for (int nt = 0; nt < 4; nt++) {  // a overlays q (q reads done pre-B3)
        int c = n0 + 8 * nt + 2 * tg;
        float2 v2;
        v2.x = tf32r(sc[nt][0]); v2.y = tf32r(sc[nt][1]); *(float2*)&sQ[r0 * 68 + c] = v2;
        v2.x = tf32r(sc[nt][2]); v2.y = tf32r(sc[nt][3]); *(float2*)&sQ[r1 * 68 + c] = v2;
    }
    __syncthreads();  // B4

    float wgt = 1.f / (1.f + __expf(-alpha[h]));
    float asum0 = R1[r0 * 2] + R1[r0 * 2 + 1], asum1 = R1[r1 * 2] + R1[r1 * 2 + 1];
    float L0 = R4[r0 * 2] + R4[r0 * 2 + 1], L1 = R4[r1 * 2] + R4[r1 * 2 + 1];
    float den0 = fmaxf(wgt * fmaxf(asum0, EPSV) + fmaxf(L0, EPSV), EPSV);
    float den1 = fmaxf(wgt * fmaxf(asum1, EPSV) + fmaxf(L1, EPSV), EPSV);

    // sm = a @ v
    float sm_[4][4] = {};
    wgemm<64, 68, 72, false>(sQ, sB, sm_, m0, n0, g, tg);

    // lin = phi_q @ S (streamed in 32-row chunks)
    float li[4][4] = {};
#pragma unroll 1
    for (int c = 0; c < 4; c++) {
#pragma unroll
        for (int kk = 0; kk < 32; kk += 8) {
            float a[4];
            ldA(sPhi, 132, m0, c * 32 + kk, g, tg, a);
#pragma unroll
            for (int nt = 0; nt < 4; nt++) {
                float b[2];
                ldB(sS, 72, kk, n0 + 8 * nt, g, tg, b);
                mma8(li[nt], a, b);
            }
        }
        __syncthreads();  // chunk consumed
        if (c < 3) {
            for (int i = t; i < 2048; i += 256)
                sS[(i >> 6) * 72 + (i & 63)] = tf32r(g_dS[sb + (size_t)(c + 1) * 2048 + i]);
            __syncthreads();  // chunk ready
        }
    }

    float id0 = 1.f / den0, id1 = 1.f / den1;
#pragma unroll
    for (int nt = 0; nt < 4; nt++) {
        int c = n0 + 8 * nt + 2 * tg;
        float2 o0, o1;
        o0.x = (wgt * sm_[nt][0] + li[nt][0]) * id0;
        o0.y = (wgt * sm_[nt][1] + li[nt][1]) * id0;
        o1.x = (wgt * sm_[nt][2] + li[nt][2]) * id1;
        o1.y = (wgt * sm_[nt][3] + li[nt][3]) * id1;
        *(float2*)&out[xb + (size_t)r0 * 64 + c] = o0;
        *(float2*)&out[xb + (size_t)r1 * 64 + c] = o1;
    }
}

extern "C" void kernel_launch(void* const* d_in, const int* in_sizes, int n_in,
                              void* d_out, int out_size) {
    const float* Q = (const float*)d_in[0];
    const float* K = (const float*)d_in[1];
    const float* V = (const float*)d_in[2];
    const float* W = (const float*)d_in[3];
    const float* A = (const float*)d_in[4];
    float* out = (float*)d_out;

    cudaFuncSetAttribute(phase1_kernel, cudaFuncAttributeMaxDynamicSharedMemorySize, 71680);
    cudaFuncSetAttribute(phase2_kernel, cudaFuncAttributeMaxDynamicSharedMemorySize, 98816);

    phase1_kernel<<<BH * NB, 256, 71680>>>(K, V, W);
    scanS_kernel<<<dim3(8, BH), 256>>>();
    scanZ_kernel<<<BH, 128>>>();
    phase2_kernel<<<BH * NB, 256, 98816>>>(Q, K, V, W, A, out);
}

// round 9
// speedup vs baseline: 2.4120x; 1.4418x over previous
#include <cuda_runtime.h>
#include <cstdint>

#define NB 64
#define F2 128
#define HH 16
#define LL 4096
#define BH 32
#define EPSV 1e-6f

__device__ float g_dS[(size_t)BH * NB * F2 * 64];  // 67 MB scratch
__device__ float g_dZ[(size_t)BH * NB * F2];       // 1 MB

__device__ __forceinline__ float tf32r(float x) {
    unsigned r;
    asm("cvt.rna.tf32.f32 %0, %1;" : "=r"(r) : "f"(x));
    return __uint_as_float(r);
}

__device__ __forceinline__ void mma8(float* c, const float* a, const float* b) {
    asm volatile(
        "mma.sync.aligned.m16n8k8.row.col.f32.tf32.tf32.f32 "
        "{%0,%1,%2,%3},{%4,%5,%6,%7},{%8,%9},{%0,%1,%2,%3};"
        : "+f"(c[0]), "+f"(c[1]), "+f"(c[2]), "+f"(c[3])
        : "r"(__float_as_uint(a[0])), "r"(__float_as_uint(a[1])),
          "r"(__float_as_uint(a[2])), "r"(__float_as_uint(a[3])),
          "r"(__float_as_uint(b[0])), "r"(__float_as_uint(b[1])));
}

__device__ __forceinline__ float rmax4(float x) {
    x = fmaxf(x, __shfl_xor_sync(0xffffffffu, x, 1));
    x = fmaxf(x, __shfl_xor_sync(0xffffffffu, x, 2));
    return x;
}
__device__ __forceinline__ float rsum4(float x) {
    x += __shfl_xor_sync(0xffffffffu, x, 1);
    x += __shfl_xor_sync(0xffffffffu, x, 2);
    return x;
}

// A fragment, row-major A[m][k] in smem, stride ld (ld % 32 == 4 -> conflict-free)
__device__ __forceinline__ void ldA(const float* S, int ld, int m0, int k0, int g, int t, float* a) {
    const float* p = S + (m0 + g) * ld + k0 + t;
    a[0] = p[0]; a[1] = p[8 * ld]; a[2] = p[4]; a[3] = p[8 * ld + 4];
}
// B fragment from smem row-major S[k][n], stride ld (ld % 32 == 8), with tf32 cvt
__device__ __forceinline__ void ldB_sc(const float* S, int ld, int k0, int n0, int g, int t, float* b) {
    const float* p = S + (k0 + t) * ld + n0 + g;
    b[0] = tf32r(p[0]); b[1] = tf32r(p[4 * ld]);
}
// B fragment, B[k][n] = S[n][k] (transposed smem source), stride ld (ld % 32 == 4)
__device__ __forceinline__ void ldBT(const float* S, int ld, int k0, int n0, int g, int t, float* b) {
    const float* p = S + (n0 + g) * ld + k0 + t;
    b[0] = p[0]; b[1] = p[4];
}
// B fragment from GLOBAL row-major P[k][n] with ld=64, tf32 cvt
__device__ __forceinline__ void ldB_g(const float* P, int k0, int n0, int g, int t, float* b) {
    const float* p = P + (k0 + t) * 64 + n0 + g;
    b[0] = tf32r(p[0]); b[1] = tf32r(p[4 * 64]);
}

__device__ __forceinline__ void cp16(const float* dst_smem, const float* src_g) {
    unsigned d = (unsigned)__cvta_generic_to_shared(dst_smem);
    asm volatile("cp.async.cg.shared.global [%0], [%1], 16;" :: "r"(d), "l"(src_g));
}
#define CP_COMMIT() asm volatile("cp.async.commit_group;")
#define CP_WAIT0()  asm volatile("cp.async.wait_group 0;")

// ======================= Phase 1: dS = phi_k^T v, dZ = colsum phi_k ==============
__global__ void __launch_bounds__(256, 3)
phase1_kernel(const float* __restrict__ K, const float* __restrict__ V,
              const float* __restrict__ W) {
    extern __shared__ float smem[];
    float* sK = smem;          // 64*68 = 4352 : k (tf32)
    float* sV = sK + 4352;     // 64*72 = 4608 : v (cp.async raw fp32)
    float* sPT = sV + 4608;    // 128*68 = 8704 : phi TRANSPOSED [f][s]
                               //  -> 17664 floats = 70656 B

    int t = threadIdx.x, w = t >> 5, lane = t & 31, g = lane >> 2, tg = lane & 3;
    int bid = blockIdx.x, bh = bid >> 6, n = bid & 63, h = bh & (HH - 1);
    size_t xb = ((size_t)bh * LL + (size_t)n * 64) * 64;
    const float* Wg = W + h * 4096;

    // v: cp.async from the start (own region, no overlay)
#pragma unroll
    for (int r = 0; r < 4; r++) {
        int idx = t + 256 * r;                 // 0..1023 (16B units)
        int row = idx >> 4, c4 = (idx & 15) * 4;
        cp16(&sV[row * 72 + c4], V + xb + (size_t)row * 64 + c4);
    }
    CP_COMMIT();

    for (int i = t; i < 4096; i += 256)
        sK[(i >> 6) * 68 + (i & 63)] = tf32r(K[xb + i]);
    __syncthreads();  // B0

    if (w < 4) {
        int m0 = 16 * w, r0 = m0 + g, r1 = r0 + 8;
        float u[8][4] = {};
#pragma unroll
        for (int k0 = 0; k0 < 64; k0 += 8) {
            float a[4];
            ldA(sK, 68, m0, k0, g, tg, a);
#pragma unroll
            for (int nt = 0; nt < 8; nt++) {
                float b[2];
                ldB_g(Wg, k0, 8 * nt, g, tg, b);
                mma8(u[nt], a, b);
            }
        }
        // in-warp softmax (full row in 4 tg-lanes), two-pass exp
        float hi0 = -3e38f, hi1 = -3e38f, lo0 = 3e38f, lo1 = 3e38f;
#pragma unroll
        for (int nt = 0; nt < 8; nt++) {
            hi0 = fmaxf(hi0, fmaxf(u[nt][0], u[nt][1]));
            lo0 = fminf(lo0, fminf(u[nt][0], u[nt][1]));
            hi1 = fmaxf(hi1, fmaxf(u[nt][2], u[nt][3]));
            lo1 = fminf(lo1, fminf(u[nt][2], u[nt][3]));
        }
        hi0 = rmax4(hi0); hi1 = rmax4(hi1);
        lo0 = -rmax4(-lo0); lo1 = -rmax4(-lo1);
        float sp0 = 0.f, sp1 = 0.f, sn0 = 0.f, sn1 = 0.f;
#pragma unroll
        for (int nt = 0; nt < 8; nt++) {
            sp0 += __expf(u[nt][0] - hi0) + __expf(u[nt][1] - hi0);
            sn0 += __expf(lo0 - u[nt][0]) + __expf(lo0 - u[nt][1]);
            sp1 += __expf(u[nt][2] - hi1) + __expf(u[nt][3] - hi1);
            sn1 += __expf(lo1 - u[nt][2]) + __expf(lo1 - u[nt][3]);
        }
        sp0 = rsum4(sp0); sp1 = rsum4(sp1); sn0 = rsum4(sn0); sn1 = rsum4(sn1);
        float rp0 = 1.f / sp0, rp1 = 1.f / sp1, rn0 = 1.f / sn0, rn1 = 1.f / sn1;
#pragma unroll
        for (int nt = 0; nt < 8; nt++) {
            int c = 8 * nt + 2 * tg;
            sPT[c * 68 + r0]        = tf32r(__expf(u[nt][0] - hi0) * rp0);
            sPT[(c + 1) * 68 + r0]  = tf32r(__expf(u[nt][1] - hi0) * rp0);
            sPT[(64 + c) * 68 + r0] = tf32r(__expf(lo0 - u[nt][0]) * rn0);
            sPT[(65 + c) * 68 + r0] = tf32r(__expf(lo0 - u[nt][1]) * rn0);
            sPT[c * 68 + r1]        = tf32r(__expf(u[nt][2] - hi1) * rp1);
            sPT[(c + 1) * 68 + r1]  = tf32r(__expf(u[nt][3] - hi1) * rp1);
            sPT[(64 + c) * 68 + r1] = tf32r(__expf(lo1 - u[nt][2]) * rn1);
            sPT[(65 + c) * 68 + r1] = tf32r(__expf(lo1 - u[nt][3]) * rn1);
        }
    }
    CP_WAIT0();
    __syncthreads();  // B1: phi^T ready, v ready

    // dS GEMM: warp w -> f-rows 16w..16w+15, all 64 d-cols. A = phi^T, B = v.
    int m0 = 16 * w;
    float acc[8][4] = {};
#pragma unroll
    for (int k0 = 0; k0 < 64; k0 += 8) {
        float a[4];
        ldA(sPT, 68, m0, k0, g, tg, a);
#pragma unroll
        for (int nt = 0; nt < 8; nt++) {
            float b[2];
            ldB_sc(sV, 72, k0, 8 * nt, g, tg, b);
            mma8(acc[nt], a, b);
        }
    }
    size_t sb = (size_t)(bh * NB + n) * F2 * 64;
#pragma unroll
    for (int nt = 0; nt < 8; nt++) {
        int c = 8 * nt + 2 * tg;
        float2 o;
        o.x = acc[nt][0]; o.y = acc[nt][1];
        *(float2*)&g_dS[sb + (size_t)(m0 + g) * 64 + c] = o;
        o.x = acc[nt][2]; o.y = acc[nt][3];
        *(float2*)&g_dS[sb + (size_t)(m0 + g + 8) * 64 + c] = o;
    }
    // dZ: row-sum of phi^T
    if (t < 128) {
        float z = 0.f;
#pragma unroll 8
        for (int s = 0; s < 64; s++) z += sPT[t * 68 + s];
        g_dZ[(size_t)(bh * NB + n) * F2 + t] = z;
    }
}

// ======================= Exclusive prefix scans over n (in-place) ================
__global__ void scanS_kernel() {
    int bh = blockIdx.y;
    int e = blockIdx.x * 256 + threadIdx.x;  // float4 index 0..2047
    float4* p = (float4*)g_dS;
    size_t base = (size_t)bh * NB * 2048 + e;
    float4 run = make_float4(0.f, 0.f, 0.f, 0.f);
#pragma unroll 8
    for (int n = 0; n < NB; n++) {
        float4 x = p[base + (size_t)n * 2048];
        p[base + (size_t)n * 2048] = run;
        run.x += x.x; run.y += x.y; run.z += x.z; run.w += x.w;
    }
}

__global__ void scanZ_kernel() {
    int bh = blockIdx.x;
    int f = threadIdx.x;
    size_t base = (size_t)bh * NB * F2 + f;
    float run = 0.f;
#pragma unroll 8
    for (int n = 0; n < NB; n++) {
        float x = g_dZ[base + (size_t)n * F2];
        g_dZ[base + (size_t)n * F2] = run;
        run += x;
    }
}

// ======================= Phase 2: outputs ========================================
__global__ void __launch_bounds__(256, 3)
phase2_kernel(const float* __restrict__ Q, const float* __restrict__ K,
              const float* __restrict__ V, const float* __restrict__ W,
              const float* __restrict__ alpha, float* __restrict__ out) {
    extern __shared__ float smem[];
    float* sQV  = smem;            // 4608: q (stride 68) -> v (stride 72, cp.async)
    float* sKA  = sQV + 4608;      // 4352: k (68) -> a (68)
    float* sPhi = sKA + 4352;      // 64*132 = 8448
    float* sZ   = sPhi + 8448;     // 128
    float* sLd  = sZ + 128;        // 64: lin_den per row
    float* sAs  = sLd + 64;        // 64: softmax den per row
                                   //  -> 17664 floats = 70656 B

    int t = threadIdx.x, w = t >> 5, lane = t & 31, g = lane >> 2, tg = lane & 3;
    int bid = blockIdx.x, bh = bid >> 6, n = bid & 63, h = bh & (HH - 1);
    size_t xb = ((size_t)bh * LL + (size_t)n * 64) * 64;
    size_t zb = (size_t)(bh * NB + n) * F2;
    const float* Sg = g_dS + (size_t)(bh * NB + n) * F2 * 64;
    const float* Wg = W + h * 4096;

    if (t < 128) sZ[t] = g_dZ[zb + t];
    for (int i = t; i < 4096; i += 256) {
        int r = i >> 6, c = i & 63;
        sQV[r * 68 + c] = tf32r(Q[xb + i]);
        sKA[r * 68 + c] = tf32r(K[xb + i]);
    }
    __syncthreads();  // B0

    if (w < 4) {
        // ---- u = q @ W (full-width rows 16w..16w+15), phi + lin_den ----
        int m0 = 16 * w, r0 = m0 + g, r1 = r0 + 8;
        float u[8][4] = {};
#pragma unroll
        for (int k0 = 0; k0 < 64; k0 += 8) {
            float a[4];
            ldA(sQV, 68, m0, k0, g, tg, a);
#pragma unroll
            for (int nt = 0; nt < 8; nt++) {
                float b[2];
                ldB_g(Wg, k0, 8 * nt, g, tg, b);
                mma8(u[nt], a, b);
            }
        }
        float hi0 = -3e38f, hi1 = -3e38f, lo0 = 3e38f, lo1 = 3e38f;
#pragma unroll
        for (int nt = 0; nt < 8; nt++) {
            hi0 = fmaxf(hi0, fmaxf(u[nt][0], u[nt][1]));
            lo0 = fminf(lo0, fminf(u[nt][0], u[nt][1]));
            hi1 = fmaxf(hi1, fmaxf(u[nt][2], u[nt][3]));
            lo1 = fminf(lo1, fminf(u[nt][2], u[nt][3]));
        }
        hi0 = rmax4(hi0); hi1 = rmax4(hi1);
        lo0 = -rmax4(-lo0); lo1 = -rmax4(-lo1);
        float sp0 = 0.f, sp1 = 0.f, sn0 = 0.f, sn1 = 0.f;
#pragma unroll
        for (int nt = 0; nt < 8; nt++) {
            sp0 += __expf(u[nt][0] - hi0) + __expf(u[nt][1] - hi0);
            sn0 += __expf(lo0 - u[nt][0]) + __expf(lo0 - u[nt][1]);
            sp1 += __expf(u[nt][2] - hi1) + __expf(u[nt][3] - hi1);
            sn1 += __expf(lo1 - u[nt][2]) + __expf(lo1 - u[nt][3]);
        }
        sp0 = rsum4(sp0); sp1 = rsum4(sp1); sn0 = rsum4(sn0); sn1 = rsum4(sn1);
        float rp0 = 1.f / sp0, rp1 = 1.f / sp1, rn0 = 1.f / sn0, rn1 = 1.f / sn1;
        float ld0 = 0.f, ld1 = 0.f;
#pragma unroll
        for (int nt = 0; nt < 8; nt++) {
            int c = 8 * nt + 2 * tg;
            float p00 = __expf(u[nt][0] - hi0) * rp0, p01 = __expf(u[nt][1] - hi0) * rp0;
            float q00 = __expf(lo0 - u[nt][0]) * rn0, q01 = __expf(lo0 - u[nt][1]) * rn0;
            float p10 = __expf(u[nt][2] - hi1) * rp1, p11 = __expf(u[nt][3] - hi1) * rp1;
            float q10 = __expf(lo1 - u[nt][2]) * rn1, q11 = __expf(lo1 - u[nt][3]) * rn1;
            float2 v2;
            v2.x = tf32r(p00); v2.y = tf32r(p01); *(float2*)&sPhi[r0 * 132 + c] = v2;
            v2.x = tf32r(q00); v2.y = tf32r(q01); *(float2*)&sPhi[r0 * 132 + 64 + c] = v2;
            v2.x = tf32r(p10); v2.y = tf32r(p11); *(float2*)&sPhi[r1 * 132 + c] = v2;
            v2.x = tf32r(q10); v2.y = tf32r(q11); *(float2*)&sPhi[r1 * 132 + 64 + c] = v2;
            ld0 += p00 * sZ[c] + p01 * sZ[c + 1] + q00 * sZ[64 + c] + q01 * sZ[65 + c];
            ld1 += p10 * sZ[c] + p11 * sZ[c + 1] + q10 * sZ[64 + c] + q11 * sZ[65 + c];
        }
        ld0 = rsum4(ld0); ld1 = rsum4(ld1);
        if (tg == 0) { sLd[r0] = ld0; sLd[r1] = ld1; }
    } else {
        // ---- scores = q @ k^T (full-width rows), softmax -> a over k ----
        int m0 = 16 * (w - 4), r0 = m0 + g, r1 = r0 + 8;
        float sc[8][4] = {};
#pragma unroll
        for (int k0 = 0; k0 < 64; k0 += 8) {
            float a[4];
            ldA(sQV, 68, m0, k0, g, tg, a);
#pragma unroll
            for (int nt = 0; nt < 8; nt++) {
                float b[2];
                ldBT(sKA, 68, k0, 8 * nt, g, tg, b);
                mma8(sc[nt], a, b);
            }
        }
        float mx0 = -3e38f, mx1 = -3e38f;
#pragma unroll
        for (int nt = 0; nt < 8; nt++) {
            sc[nt][0] *= 0.125f; sc[nt][1] *= 0.125f;
            sc[nt][2] *= 0.125f; sc[nt][3] *= 0.125f;
            mx0 = fmaxf(mx0, fmaxf(sc[nt][0], sc[nt][1]));
            mx1 = fmaxf(mx1, fmaxf(sc[nt][2], sc[nt][3]));
        }
        mx0 = rmax4(mx0); mx1 = rmax4(mx1);
        float as0 = 0.f, as1 = 0.f;
#pragma unroll
        for (int nt = 0; nt < 8; nt++) {
            sc[nt][0] = __expf(sc[nt][0] - mx0); sc[nt][1] = __expf(sc[nt][1] - mx0);
            sc[nt][2] = __expf(sc[nt][2] - mx1); sc[nt][3] = __expf(sc[nt][3] - mx1);
            as0 += sc[nt][0] + sc[nt][1];
            as1 += sc[nt][2] + sc[nt][3];
        }
        as0 = rsum4(as0); as1 = rsum4(as1);
        if (tg == 0) { sAs[r0] = as0; sAs[r1] = as1; }
        asm volatile("bar.sync 1, 128;" ::: "memory");  // all score warps done reading k
#pragma unroll
        for (int nt = 0; nt < 8; nt++) {
            int c = 8 * nt + 2 * tg;
            float2 v2;
            v2.x = tf32r(sc[nt][0]); v2.y = tf32r(sc[nt][1]); *(float2*)&sKA[r0 * 68 + c] = v2;
            v2.x = tf32r(sc[nt][2]); v2.y = tf32r(sc[nt][3]); *(float2*)&sKA[r1 * 68 + c] = v2;
        }
    }
    __syncthreads();  // B1: phi, a, sLd, sAs visible; q,k dead

    // v: cp.async over the q region (stride 72), overlapped with the lin GEMM
#pragma unroll
    for (int r = 0; r < 4; r++) {
        int idx = t + 256 * r;
        int row = idx >> 4, c4 = (idx & 15) * 4;
        cp16(&sQV[row * 72 + c4], V + xb + (size_t)row * 64 + c4);
    }
    CP_COMMIT();

    int mt = w >> 1, nh = w & 1, m0 = 16 * mt, n0 = 32 * nh, r0 = m0 + g, r1 = r0 + 8;

    // lin = phi_q @ S : A from smem, B direct from global (S is L2-resident)
    float li[4][4] = {};
#pragma unroll
    for (int k0 = 0; k0 < 128; k0 += 8) {
        float a[4];
        ldA(sPhi, 132, m0, k0, g, tg, a);
#pragma unroll
        for (int nt = 0; nt < 4; nt++) {
            float b[2];
            ldB_g(Sg, k0, n0 + 8 * nt, g, tg, b);
            mma8(li[nt], a, b);
        }
    }

    CP_WAIT0();
    __syncthreads();  // B2: v ready

    // sm = a @ v
    float sm_[4][4] = {};
#pragma unroll
    for (int k0 = 0; k0 < 64; k0 += 8) {
        float a[4];
        ldA(sKA, 68, m0, k0, g, tg, a);
#pragma unroll
        for (int nt = 0; nt < 4; nt++) {
            float b[2];
            ldB_sc(sQV, 72, k0, n0 + 8 * nt, g, tg, b);
            mma8(sm_[nt], a, b);
        }
    }

    float wgt = 1.f / (1.f + __expf(-alpha[h]));
    float den0 = fmaxf(wgt * fmaxf(sAs[r0], EPSV) + fmaxf(sLd[r0], EPSV), EPSV);
    float den1 = fmaxf(wgt * fmaxf(sAs[r1], EPSV) + fmaxf(sLd[r1], EPSV), EPSV);
    float id0 = 1.f / den0, id1 = 1.f / den1;
#pragma unroll
    for (int nt = 0; nt < 4; nt++) {
        int c = n0 + 8 * nt + 2 * tg;
        float2 o0, o1;
        o0.x = (wgt * sm_[nt][0] + li[nt][0]) * id0;
        o0.y = (wgt * sm_[nt][1] + li[nt][1]) * id0;
        o1.x = (wgt * sm_[nt][2] + li[nt][2]) * id1;
        o1.y = (wgt * sm_[nt][3] + li[nt][3]) * id1;
        *(float2*)&out[xb + (size_t)r0 * 64 + c] = o0;
        *(float2*)&out[xb + (size_t)r1 * 64 + c] = o1;
    }
}

extern "C" void kernel_launch(void* const* d_in, const int* in_sizes, int n_in,
                              void* d_out, int out_size) {
    const float* Q = (const float*)d_in[0];
    const float* K = (const float*)d_in[1];
    const float* V = (const float*)d_in[2];
    const float* W = (const float*)d_in[3];
    const float* A = (const float*)d_in[4];
    float* out = (float*)d_out;

    cudaFuncSetAttribute(phase1_kernel, cudaFuncAttributeMaxDynamicSharedMemorySize, 70656);
    cudaFuncSetAttribute(phase2_kernel, cudaFuncAttributeMaxDynamicSharedMemorySize, 70656);

    phase1_kernel<<<BH * NB, 256, 70656>>>(K, V, W);
    scanS_kernel<<<dim3(8, BH), 256>>>();
    scanZ_kernel<<<BH, 128>>>();
    phase2_kernel<<<BH * NB, 256, 70656>>>(Q, K, V, W, A, out);
}

// round 10
// speedup vs baseline: 4.4953x; 1.8637x over previous
#include <cuda_runtime.h>
#include <cuda_fp16.h>
#include <cstdint>

#define NB 64
#define HH 16
#define LL 4096
#define BH 32
#define EPSV 1e-6f
#define BLKF 8320   // per-block floats in g_dS: 64x128 S^T + 128 Z

__device__ float g_dS[(size_t)BH * NB * BLKF];   // 68 MB scratch
__device__ uint32_t g_WT[HH * 2048];             // W^T fp16 [h][f][d/2]

__device__ __forceinline__ uint32_t pk(float a, float b) {
    __half2 h = __floats2half2_rn(a, b);
    return *(uint32_t*)&h;
}

__device__ __forceinline__ void mma16(float* c, const uint32_t* a, const uint32_t* b) {
    asm volatile(
        "mma.sync.aligned.m16n8k16.row.col.f32.f16.f16.f32 "
        "{%0,%1,%2,%3},{%4,%5,%6,%7},{%8,%9},{%0,%1,%2,%3};"
        : "+f"(c[0]), "+f"(c[1]), "+f"(c[2]), "+f"(c[3])
        : "r"(a[0]), "r"(a[1]), "r"(a[2]), "r"(a[3]), "r"(b[0]), "r"(b[1]));
}

// x4 non-trans: tiles (r0,k0),(r0+8,k0),(r0,k0+8),(r0+8,k0+8); S = half2 array, ld2 in half2
__device__ __forceinline__ void ldsm4(const uint32_t* S, int ld2, int r0, int k0, uint32_t* d) {
    int lane = threadIdx.x & 31, q = lane >> 3, r = lane & 7;
    const uint32_t* p = S + (r0 + r + 8 * (q & 1)) * ld2 + (k0 >> 1) + 4 * (q >> 1);
    unsigned a = (unsigned)__cvta_generic_to_shared(p);
    asm volatile("ldmatrix.sync.aligned.m8n8.x4.shared.b16 {%0,%1,%2,%3},[%4];"
                 : "=r"(d[0]), "=r"(d[1]), "=r"(d[2]), "=r"(d[3]) : "r"(a));
}
// x4 trans from natural [k][n]: tiles (k0,n0),(k0,n0+8),(k0+8,n0),(k0+8,n0+8)
__device__ __forceinline__ void ldsm4t(const uint32_t* S, int ld2, int k0, int n0, uint32_t* d) {
    int lane = threadIdx.x & 31, q = lane >> 3, r = lane & 7;
    const uint32_t* p = S + (k0 + r + 8 * (q >> 1)) * ld2 + (n0 >> 1) + 4 * (q & 1);
    unsigned a = (unsigned)__cvta_generic_to_shared(p);
    asm volatile("ldmatrix.sync.aligned.m8n8.x4.trans.shared.b16 {%0,%1,%2,%3},[%4];"
                 : "=r"(d[0]), "=r"(d[1]), "=r"(d[2]), "=r"(d[3]) : "r"(a));
}

__device__ __forceinline__ float rmax4(float x) {
    x = fmaxf(x, __shfl_xor_sync(0xffffffffu, x, 1));
    x = fmaxf(x, __shfl_xor_sync(0xffffffffu, x, 2));
    return x;
}
__device__ __forceinline__ float rsum4(float x) {
    x += __shfl_xor_sync(0xffffffffu, x, 1);
    x += __shfl_xor_sync(0xffffffffu, x, 2);
    return x;
}

__device__ __forceinline__ void cp16(void* dst_smem, const void* src_g) {
    unsigned d = (unsigned)__cvta_generic_to_shared(dst_smem);
    asm volatile("cp.async.cg.shared.global [%0], [%1], 16;" :: "r"(d), "l"(src_g));
}
#define CP_COMMIT() asm volatile("cp.async.commit_group;")
#define CP_WAIT0()  asm volatile("cp.async.wait_group 0;")

// ======================= Prep: W^T -> fp16 global ================================
__global__ void prep_kernel(const float* __restrict__ W) {
    int h = blockIdx.x, t = threadIdx.x;
    const float* Wh = W + h * 4096;
#pragma unroll
    for (int i = 0; i < 8; i++) {
        int idx = t + 256 * i;              // 0..2047
        int f = idx >> 5, j = idx & 31;     // WT[f][d-pair j]
        g_WT[h * 2048 + f * 32 + j] = pk(Wh[(2 * j) * 64 + f], Wh[(2 * j + 1) * 64 + f]);
    }
}

// ======================= Phase 1: S^T block deltas + Z ===========================
__global__ void __launch_bounds__(256, 3)
phase1_kernel(const float* __restrict__ K, const float* __restrict__ V) {
    extern __shared__ uint32_t smu[];
    uint32_t* sK   = smu;          // [64][36] k
    uint32_t* sV   = smu + 2304;   // [64][36] v
    uint32_t* sWT  = smu + 4608;   // [64][36] W^T
    uint32_t* sPhi = smu + 6912;   // [64][68] phi   -> 11264 u32 = 45056 B

    int t = threadIdx.x, w = t >> 5, lane = t & 31, g = lane >> 2, tg = lane & 3;
    int bid = blockIdx.x, bh = bid >> 6, n = bid & 63, h = bh & (HH - 1);
    size_t xb = ((size_t)bh * LL + (size_t)n * 64) * 64;
    size_t sb = (size_t)bid * BLKF;

#pragma unroll
    for (int i = 0; i < 2; i++) {
        int idx = t + 256 * i;              // 0..511
        int f = idx >> 3, j = idx & 7;
        cp16(sWT + f * 36 + j * 4, g_WT + h * 2048 + f * 32 + j * 4);
    }
    CP_COMMIT();
#pragma unroll
    for (int i = 0; i < 8; i++) {
        int idx = t + 256 * i;              // 0..2047
        int s = idx >> 5, j = idx & 31;
        float2 kx = *(const float2*)&K[xb + s * 64 + 2 * j];
        float2 vx = *(const float2*)&V[xb + s * 64 + 2 * j];
        sK[s * 36 + j] = pk(kx.x, kx.y);
        sV[s * 36 + j] = pk(vx.x, vx.y);
    }
    CP_WAIT0();
    __syncthreads();  // B0

    if (w < 4) {
        int m0 = 16 * w, r0 = m0 + g, r1 = r0 + 8;
        float u[8][4] = {};
#pragma unroll
        for (int k0 = 0; k0 < 64; k0 += 16) {
            uint32_t a[4]; ldsm4(sK, 36, m0, k0, a);
#pragma unroll
            for (int p = 0; p < 4; p++) {
                uint32_t b[4]; ldsm4(sWT, 36, 16 * p, k0, b);
                uint32_t b0[2] = {b[0], b[2]}, b1[2] = {b[1], b[3]};
                mma16(u[2 * p], a, b0);
                mma16(u[2 * p + 1], a, b1);
            }
        }
        float hi0 = -3e38f, hi1 = -3e38f, lo0 = 3e38f, lo1 = 3e38f;
#pragma unroll
        for (int nt = 0; nt < 8; nt++) {
            hi0 = fmaxf(hi0, fmaxf(u[nt][0], u[nt][1]));
            lo0 = fminf(lo0, fminf(u[nt][0], u[nt][1]));
            hi1 = fmaxf(hi1, fmaxf(u[nt][2], u[nt][3]));
            lo1 = fminf(lo1, fminf(u[nt][2], u[nt][3]));
        }
        hi0 = rmax4(hi0); hi1 = rmax4(hi1);
        lo0 = -rmax4(-lo0); lo1 = -rmax4(-lo1);
        float sp0 = 0.f, sp1 = 0.f, sn0 = 0.f, sn1 = 0.f;
#pragma unroll
        for (int nt = 0; nt < 8; nt++) {
            sp0 += __expf(u[nt][0] - hi0) + __expf(u[nt][1] - hi0);
            sn0 += __expf(lo0 - u[nt][0]) + __expf(lo0 - u[nt][1]);
            sp1 += __expf(u[nt][2] - hi1) + __expf(u[nt][3] - hi1);
            sn1 += __expf(lo1 - u[nt][2]) + __expf(lo1 - u[nt][3]);
        }
        sp0 = rsum4(sp0); sp1 = rsum4(sp1); sn0 = rsum4(sn0); sn1 = rsum4(sn1);
        float rp0 = 1.f / sp0, rp1 = 1.f / sp1, rn0 = 1.f / sn0, rn1 = 1.f / sn1;
#pragma unroll
        for (int nt = 0; nt < 8; nt++) {
            int j = 4 * nt + tg;
            sPhi[r0 * 68 + j]      = pk(__expf(u[nt][0] - hi0) * rp0, __expf(u[nt][1] - hi0) * rp0);
            sPhi[r0 * 68 + 32 + j] = pk(__expf(lo0 - u[nt][0]) * rn0, __expf(lo0 - u[nt][1]) * rn0);
            sPhi[r1 * 68 + j]      = pk(__expf(u[nt][2] - hi1) * rp1, __expf(u[nt][3] - hi1) * rp1);
            sPhi[r1 * 68 + 32 + j] = pk(__expf(lo1 - u[nt][2]) * rn1, __expf(lo1 - u[nt][3]) * rn1);
        }
    }
    __syncthreads();  // B1: phi ready

    // dS^T[d][f] = sum_s v[s][d] * phi[s][f]; A = v^T (trans), B = phi (trans)
    int mt = w >> 1, nh = w & 1, m0 = 16 * mt, n0 = 64 * nh;
    float acc[8][4] = {};
#pragma unroll
    for (int k0 = 0; k0 < 64; k0 += 16) {
        uint32_t a[4]; ldsm4t(sV, 36, k0, m0, a);
#pragma unroll
        for (int p = 0; p < 4; p++) {
            uint32_t b[4]; ldsm4t(sPhi, 68, k0, n0 + 16 * p, b);
            uint32_t b0[2] = {b[0], b[2]}, b1[2] = {b[1], b[3]};
            mma16(acc[2 * p], a, b0);
            mma16(acc[2 * p + 1], a, b1);
        }
    }
#pragma unroll
    for (int nt = 0; nt < 8; nt++) {
        int c = n0 + 8 * nt + 2 * tg;
        float2 o;
        o.x = acc[nt][0]; o.y = acc[nt][1];
        *(float2*)&g_dS[sb + (size_t)(m0 + g) * 128 + c] = o;
        o.x = acc[nt][2]; o.y = acc[nt][3];
        *(float2*)&g_dS[sb + (size_t)(m0 + g + 8) * 128 + c] = o;
    }
    if (t < 64) {  // Z row: column sums of phi
        float zx = 0.f, zy = 0.f;
#pragma unroll 8
        for (int s = 0; s < 64; s++) {
            float2 f2 = __half22float2(*(__half2*)&sPhi[s * 68 + t]);
            zx += f2.x; zy += f2.y;
        }
        float2 o; o.x = zx; o.y = zy;
        *(float2*)&g_dS[sb + 8192 + 2 * t] = o;
    }
}

// ======================= Exclusive prefix scan (S^T + Z fused) ===================
__global__ void scanS_kernel() {
    int bh = blockIdx.y;
    int e = blockIdx.x * 160 + threadIdx.x;   // 0..2079 float4 chains
    float4* p = (float4*)g_dS;
    size_t base = (size_t)bh * NB * 2080 + e;
    float4 run = make_float4(0.f, 0.f, 0.f, 0.f);
#pragma unroll 8
    for (int n = 0; n < NB; n++) {
        float4 x = p[base + (size_t)n * 2080];
        p[base + (size_t)n * 2080] = run;
        run.x += x.x; run.y += x.y; run.z += x.z; run.w += x.w;
    }
}

// ======================= Phase 2: outputs ========================================
__global__ void __launch_bounds__(256, 3)
phase2_kernel(const float* __restrict__ Q, const float* __restrict__ K,
              const float* __restrict__ V, const float* __restrict__ alpha,
              float* __restrict__ out) {
    extern __shared__ uint32_t smu[];
    uint32_t* sQ   = smu;           // [64][36] q
    uint32_t* sA   = smu + 2304;    // [64][36] a
    uint32_t* sKV  = smu + 4608;    // [64][36] k -> v
    uint32_t* sPhi = smu + 6912;    // [64][68] phi
    uint32_t* sWS  = smu + 11264;   // [64][36] W^T -> [64][68] S^T
    float*    sZf  = (float*)(smu + 15616);  // 128
    float*    sLd  = (float*)(smu + 15744);  // 64
    float*    sAs  = (float*)(smu + 15808);  // 64  -> 15872 u32 = 63488 B

    int t = threadIdx.x, w = t >> 5, lane = t & 31, g = lane >> 2, tg = lane & 3;
    int bid = blockIdx.x, bh = bid >> 6, n = bid & 63, h = bh & (HH - 1);
    size_t xb = ((size_t)bh * LL + (size_t)n * 64) * 64;
    const float* Sg = g_dS + (size_t)bid * BLKF;

#pragma unroll
    for (int i = 0; i < 2; i++) {
        int idx = t + 256 * i;
        int f = idx >> 3, j = idx & 7;
        cp16(sWS + f * 36 + j * 4, g_WT + h * 2048 + f * 32 + j * 4);
    }
    CP_COMMIT();
    if (t < 64) *(float2*)&sZf[2 * t] = *(const float2*)&Sg[8192 + 2 * t];
#pragma unroll
    for (int i = 0; i < 8; i++) {
        int idx = t + 256 * i;
        int s = idx >> 5, j = idx & 31;
        float2 qx = *(const float2*)&Q[xb + s * 64 + 2 * j];
        float2 kx = *(const float2*)&K[xb + s * 64 + 2 * j];
        sQ[s * 36 + j] = pk(qx.x, qx.y);
        sKV[s * 36 + j] = pk(kx.x, kx.y);
    }
    CP_WAIT0();
    __syncthreads();  // B0

    if (w < 4) {
        // u = q @ W, hedgehog phi + lin_den
        int m0 = 16 * w, r0 = m0 + g, r1 = r0 + 8;
        float u[8][4] = {};
#pragma unroll
        for (int k0 = 0; k0 < 64; k0 += 16) {
            uint32_t a[4]; ldsm4(sQ, 36, m0, k0, a);
#pragma unroll
            for (int p = 0; p < 4; p++) {
                uint32_t b[4]; ldsm4(sWS, 36, 16 * p, k0, b);
                uint32_t b0[2] = {b[0], b[2]}, b1[2] = {b[1], b[3]};
                mma16(u[2 * p], a, b0);
                mma16(u[2 * p + 1], a, b1);
            }
        }
        float hi0 = -3e38f, hi1 = -3e38f, lo0 = 3e38f, lo1 = 3e38f;
#pragma unroll
        for (int nt = 0; nt < 8; nt++) {
            hi0 = fmaxf(hi0, fmaxf(u[nt][0], u[nt][1]));
            lo0 = fminf(lo0, fminf(u[nt][0], u[nt][1]));
            hi1 = fmaxf(hi1, fmaxf(u[nt][2], u[nt][3]));
            lo1 = fminf(lo1, fminf(u[nt][2], u[nt][3]));
        }
        hi0 = rmax4(hi0); hi1 = rmax4(hi1);
        lo0 = -rmax4(-lo0); lo1 = -rmax4(-lo1);
        float sp0 = 0.f, sp1 = 0.f, sn0 = 0.f, sn1 = 0.f;
#pragma unroll
        for (int nt = 0; nt < 8; nt++) {
            sp0 += __expf(u[nt][0] - hi0) + __expf(u[nt][1] - hi0);
            sn0 += __expf(lo0 - u[nt][0]) + __expf(lo0 - u[nt][1]);
            sp1 += __expf(u[nt][2] - hi1) + __expf(u[nt][3] - hi1);
            sn1 += __expf(lo1 - u[nt][2]) + __expf(lo1 - u[nt][3]);
        }
        sp0 = rsum4(sp0); sp1 = rsum4(sp1); sn0 = rsum4(sn0); sn1 = rsum4(sn1);
        float rp0 = 1.f / sp0, rp1 = 1.f / sp1, rn0 = 1.f / sn0, rn1 = 1.f / sn1;
        float ld0 = 0.f, ld1 = 0.f;
#pragma unroll
        for (int nt = 0; nt < 8; nt++) {
            int c = 8 * nt + 2 * tg, j = 4 * nt + tg;
            float p00 = __expf(u[nt][0] - hi0) * rp0, p01 = __expf(u[nt][1] - hi0) * rp0;
            float q00 = __expf(lo0 - u[nt][0]) * rn0, q01 = __expf(lo0 - u[nt][1]) * rn0;
            float p10 = __expf(u[nt][2] - hi1) * rp1, p11 = __expf(u[nt][3] - hi1) * rp1;
            float q10 = __expf(lo1 - u[nt][2]) * rn1, q11 = __expf(lo1 - u[nt][3]) * rn1;
            sPhi[r0 * 68 + j]      = pk(p00, p01);
            sPhi[r0 * 68 + 32 + j] = pk(q00, q01);
            sPhi[r1 * 68 + j]      = pk(p10, p11);
            sPhi[r1 * 68 + 32 + j] = pk(q10, q11);
            ld0 += p00 * sZf[c] + p01 * sZf[c + 1] + q00 * sZf[64 + c] + q01 * sZf[65 + c];
            ld1 += p10 * sZf[c] + p11 * sZf[c + 1] + q10 * sZf[64 + c] + q11 * sZf[65 + c];
        }
        ld0 = rsum4(ld0); ld1 = rsum4(ld1);
        if (tg == 0) { sLd[r0] = ld0; sLd[r1] = ld1; }
    } else {
        // scores = q @ k^T, softmax -> a (separate buffer, no overwrite hazard)
        int m0 = 16 * (w - 4), r0 = m0 + g, r1 = r0 + 8;
        float sc[8][4] = {};
#pragma unroll
        for (int k0 = 0; k0 < 64; k0 += 16) {
            uint32_t a[4]; ldsm4(sQ, 36, m0, k0, a);
#pragma unroll
            for (int p = 0; p < 4; p++) {
                uint32_t b[4]; ldsm4(sKV, 36, 16 * p, k0, b);
                uint32_t b0[2] = {b[0], b[2]}, b1[2] = {b[1], b[3]};
                mma16(sc[2 * p], a, b0);
                mma16(sc[2 * p + 1], a, b1);
            }
        }
        float mx0 = -3e38f, mx1 = -3e38f;
#pragma unroll
        for (int nt = 0; nt < 8; nt++) {
            sc[nt][0] *= 0.125f; sc[nt][1] *= 0.125f;
            sc[nt][2] *= 0.125f; sc[nt][3] *= 0.125f;
            mx0 = fmaxf(mx0, fmaxf(sc[nt][0], sc[nt][1]));
            mx1 = fmaxf(mx1, fmaxf(sc[nt][2], sc[nt][3]));
        }
        mx0 = rmax4(mx0); mx1 = rmax4(mx1);
        float as0 = 0.f, as1 = 0.f;
#pragma unroll
        for (int nt = 0; nt < 8; nt++) {
            sc[nt][0] = __expf(sc[nt][0] - mx0); sc[nt][1] = __expf(sc[nt][1] - mx0);
            sc[nt][2] = __expf(sc[nt][2] - mx1); sc[nt][3] = __expf(sc[nt][3] - mx1);
            as0 += sc[nt][0] + sc[nt][1];
            as1 += sc[nt][2] + sc[nt][3];
        }
        as0 = rsum4(as0); as1 = rsum4(as1);
        if (tg == 0) { sAs[r0] = as0; sAs[r1] = as1; }
#pragma unroll
        for (int nt = 0; nt < 8; nt++) {
            int j = 4 * nt + tg;
            sA[r0 * 36 + j] = pk(sc[nt][0], sc[nt][1]);
            sA[r1 * 36 + j] = pk(sc[nt][2], sc[nt][3]);
        }
    }
    __syncthreads();  // B1: phi, a, sLd, sAs ready; q/k/W dead

    // stage S^T fp16 (over W region) and v (over k region)
#pragma unroll
    for (int i = 0; i < 16; i++) {
        int idx = t + 256 * i;              // 0..4095
        int d = idx >> 6, j = idx & 63;
        float2 x = *(const float2*)&Sg[(size_t)d * 128 + 2 * j];
        sWS[d * 68 + j] = pk(x.x, x.y);
    }
#pragma unroll
    for (int i = 0; i < 8; i++) {
        int idx = t + 256 * i;
        int s = idx >> 5, j = idx & 31;
        float2 vx = *(const float2*)&V[xb + s * 64 + 2 * j];
        sKV[s * 36 + j] = pk(vx.x, vx.y);
    }
    __syncthreads();  // B2

    int mt = w >> 1, nh = w & 1, m0 = 16 * mt, n0 = 32 * nh, r0 = m0 + g, r1 = r0 + 8;

    // lin = phi @ S (B = S^T rows, non-trans), sm = a @ v (B = v natural, trans)
    float li[4][4] = {}, sm_[4][4] = {};
#pragma unroll
    for (int k0 = 0; k0 < 128; k0 += 16) {
        uint32_t a[4]; ldsm4(sPhi, 68, m0, k0, a);
#pragma unroll
        for (int p = 0; p < 2; p++) {
            uint32_t b[4]; ldsm4(sWS, 68, n0 + 16 * p, k0, b);
            uint32_t b0[2] = {b[0], b[2]}, b1[2] = {b[1], b[3]};
            mma16(li[2 * p], a, b0);
            mma16(li[2 * p + 1], a, b1);
        }
    }
#pragma unroll
    for (int k0 = 0; k0 < 64; k0 += 16) {
        uint32_t a[4]; ldsm4(sA, 36, m0, k0, a);
#pragma unroll
        for (int p = 0; p < 2; p++) {
            uint32_t b[4]; ldsm4t(sKV, 36, k0, n0 + 16 * p, b);
            uint32_t b0[2] = {b[0], b[2]}, b1[2] = {b[1], b[3]};
            mma16(sm_[2 * p], a, b0);
            mma16(sm_[2 * p + 1], a, b1);
        }
    }

    float wgt = 1.f / (1.f + __expf(-alpha[h]));
    float den0 = fmaxf(wgt * fmaxf(sAs[r0], EPSV) + fmaxf(sLd[r0], EPSV), EPSV);
    float den1 = fmaxf(wgt * fmaxf(sAs[r1], EPSV) + fmaxf(sLd[r1], EPSV), EPSV);
    float id0 = 1.f / den0, id1 = 1.f / den1;
#pragma unroll
    for (int nt = 0; nt < 4; nt++) {
        int c = n0 + 8 * nt + 2 * tg;
        float2 o0, o1;
        o0.x = (wgt * sm_[nt][0] + li[nt][0]) * id0;
        o0.y = (wgt * sm_[nt][1] + li[nt][1]) * id0;
        o1.x = (wgt * sm_[nt][2] + li[nt][2]) * id1;
        o1.y = (wgt * sm_[nt][3] + li[nt][3]) * id1;
        *(float2*)&out[xb + (size_t)r0 * 64 + c] = o0;
        *(float2*)&out[xb + (size_t)r1 * 64 + c] = o1;
    }
}

extern "C" void kernel_launch(void* const* d_in, const int* in_sizes, int n_in,
                              void* d_out, int out_size) {
    const float* Q = (const float*)d_in[0];
    const float* K = (const float*)d_in[1];
    const float* V = (const float*)d_in[2];
    const float* W = (const float*)d_in[3];
    const float* A = (const float*)d_in[4];
    float* out = (float*)d_out;

    cudaFuncSetAttribute(phase1_kernel, cudaFuncAttributeMaxDynamicSharedMemorySize, 45056);
    cudaFuncSetAttribute(phase2_kernel, cudaFuncAttributeMaxDynamicSharedMemorySize, 63488);

    prep_kernel<<<HH, 256>>>(W);
    phase1_kernel<<<BH * NB, 256, 45056>>>(K, V);
    scanS_kernel<<<dim3(13, BH), 160>>>();
    phase2_kernel<<<BH * NB, 256, 63488>>>(Q, K, V, A, out);
}

// round 11
// speedup vs baseline: 5.2857x; 1.1758x over previous
#include <cuda_runtime.h>
#include <cuda_fp16.h>
#include <cstdint>

#define NB 64
#define HH 16
#define LL 4096
#define BH 32
#define EPSV 1e-6f
#define BLKU 4160   // per-block u32 in g_dS: 64x64 S^T half2 + 64 Z half2

__device__ uint32_t g_dS[(size_t)BH * NB * BLKU];  // 34 MB fp16 scratch
__device__ uint32_t g_WT[HH * 2048];               // W^T fp16 [h][f][d/2]

__device__ __forceinline__ uint32_t pk(float a, float b) {
    __half2 h = __floats2half2_rn(a, b);
    return *(uint32_t*)&h;
}

__device__ __forceinline__ void mma16(float* c, const uint32_t* a, const uint32_t* b) {
    asm volatile(
        "mma.sync.aligned.m16n8k16.row.col.f32.f16.f16.f32 "
        "{%0,%1,%2,%3},{%4,%5,%6,%7},{%8,%9},{%0,%1,%2,%3};"
        : "+f"(c[0]), "+f"(c[1]), "+f"(c[2]), "+f"(c[3])
        : "r"(a[0]), "r"(a[1]), "r"(a[2]), "r"(a[3]), "r"(b[0]), "r"(b[1]));
}

// x4 non-trans: tiles (r0,k0),(r0+8,k0),(r0,k0+8),(r0+8,k0+8); S = half2 array, ld2 in half2
__device__ __forceinline__ void ldsm4(const uint32_t* S, int ld2, int r0, int k0, uint32_t* d) {
    int lane = threadIdx.x & 31, q = lane >> 3, r = lane & 7;
    const uint32_t* p = S + (r0 + r + 8 * (q & 1)) * ld2 + (k0 >> 1) + 4 * (q >> 1);
    unsigned a = (unsigned)__cvta_generic_to_shared(p);
    asm volatile("ldmatrix.sync.aligned.m8n8.x4.shared.b16 {%0,%1,%2,%3},[%4];"
                 : "=r"(d[0]), "=r"(d[1]), "=r"(d[2]), "=r"(d[3]) : "r"(a));
}
// x4 trans from natural [k][n]: tiles (k0,n0),(k0,n0+8),(k0+8,n0),(k0+8,n0+8)
__device__ __forceinline__ void ldsm4t(const uint32_t* S, int ld2, int k0, int n0, uint32_t* d) {
    int lane = threadIdx.x & 31, q = lane >> 3, r = lane & 7;
    const uint32_t* p = S + (k0 + r + 8 * (q >> 1)) * ld2 + (n0 >> 1) + 4 * (q & 1);
    unsigned a = (unsigned)__cvta_generic_to_shared(p);
    asm volatile("ldmatrix.sync.aligned.m8n8.x4.trans.shared.b16 {%0,%1,%2,%3},[%4];"
                 : "=r"(d[0]), "=r"(d[1]), "=r"(d[2]), "=r"(d[3]) : "r"(a));
}

__device__ __forceinline__ float rmax4(float x) {
    x = fmaxf(x, __shfl_xor_sync(0xffffffffu, x, 1));
    x = fmaxf(x, __shfl_xor_sync(0xffffffffu, x, 2));
    return x;
}
__device__ __forceinline__ float rsum4(float x) {
    x += __shfl_xor_sync(0xffffffffu, x, 1);
    x += __shfl_xor_sync(0xffffffffu, x, 2);
    return x;
}

__device__ __forceinline__ void cp16(void* dst_smem, const void* src_g) {
    unsigned d = (unsigned)__cvta_generic_to_shared(dst_smem);
    asm volatile("cp.async.cg.shared.global [%0], [%1], 16;" :: "r"(d), "l"(src_g));
}
#define CP_COMMIT() asm volatile("cp.async.commit_group;")
#define CP_WAIT0()  asm volatile("cp.async.wait_group 0;")
#define CP_WAIT1()  asm volatile("cp.async.wait_group 1;")

// ======================= Prep: W^T -> fp16 global ================================
__global__ void prep_kernel(const float* __restrict__ W) {
    int h = blockIdx.x, t = threadIdx.x;
    const float* Wh = W + h * 4096;
#pragma unroll
    for (int i = 0; i < 8; i++) {
        int idx = t + 256 * i;              // 0..2047
        int f = idx >> 5, j = idx & 31;     // WT[f][d-pair j]
        g_WT[h * 2048 + f * 32 + j] = pk(Wh[(2 * j) * 64 + f], Wh[(2 * j + 1) * 64 + f]);
    }
}

// ======================= Phase 1: fp16 S^T block deltas + Z ======================
__global__ void __launch_bounds__(256, 3)
phase1_kernel(const float* __restrict__ K, const float* __restrict__ V) {
    extern __shared__ uint32_t smu[];
    uint32_t* sK   = smu;          // [64][36] k
    uint32_t* sV   = smu + 2304;   // [64][36] v
    uint32_t* sWT  = smu + 4608;   // [64][36] W^T
    uint32_t* sPhi = smu + 6912;   // [64][68] phi   -> 11264 u32 = 45056 B

    int t = threadIdx.x, w = t >> 5, lane = t & 31, g = lane >> 2, tg = lane & 3;
    int bid = blockIdx.x, bh = bid >> 6, n = bid & 63, h = bh & (HH - 1);
    size_t xb = ((size_t)bh * LL + (size_t)n * 64) * 64;
    size_t sb = (size_t)bid * BLKU;

#pragma unroll
    for (int i = 0; i < 2; i++) {
        int idx = t + 256 * i;              // 0..511
        int f = idx >> 3, j = idx & 7;
        cp16(sWT + f * 36 + j * 4, g_WT + h * 2048 + f * 32 + j * 4);
    }
    CP_COMMIT();
#pragma unroll
    for (int i = 0; i < 8; i++) {
        int idx = t + 256 * i;              // 0..2047
        int s = idx >> 5, j = idx & 31;
        float2 kx = *(const float2*)&K[xb + s * 64 + 2 * j];
        float2 vx = *(const float2*)&V[xb + s * 64 + 2 * j];
        sK[s * 36 + j] = pk(kx.x, kx.y);
        sV[s * 36 + j] = pk(vx.x, vx.y);
    }
    CP_WAIT0();
    __syncthreads();  // B0

    if (w < 4) {
        int m0 = 16 * w, r0 = m0 + g, r1 = r0 + 8;
        float u[8][4] = {};
#pragma unroll
        for (int k0 = 0; k0 < 64; k0 += 16) {
            uint32_t a[4]; ldsm4(sK, 36, m0, k0, a);
#pragma unroll
            for (int p = 0; p < 4; p++) {
                uint32_t b[4]; ldsm4(sWT, 36, 16 * p, k0, b);
                uint32_t b0[2] = {b[0], b[2]}, b1[2] = {b[1], b[3]};
                mma16(u[2 * p], a, b0);
                mma16(u[2 * p + 1], a, b1);
            }
        }
        float hi0 = -3e38f, hi1 = -3e38f, lo0 = 3e38f, lo1 = 3e38f;
#pragma unroll
        for (int nt = 0; nt < 8; nt++) {
            hi0 = fmaxf(hi0, fmaxf(u[nt][0], u[nt][1]));
            lo0 = fminf(lo0, fminf(u[nt][0], u[nt][1]));
            hi1 = fmaxf(hi1, fmaxf(u[nt][2], u[nt][3]));
            lo1 = fminf(lo1, fminf(u[nt][2], u[nt][3]));
        }
        hi0 = rmax4(hi0); hi1 = rmax4(hi1);
        lo0 = -rmax4(-lo0); lo1 = -rmax4(-lo1);
        float sp0 = 0.f, sp1 = 0.f, sn0 = 0.f, sn1 = 0.f;
#pragma unroll
        for (int nt = 0; nt < 8; nt++) {
            sp0 += __expf(u[nt][0] - hi0) + __expf(u[nt][1] - hi0);
            sn0 += __expf(lo0 - u[nt][0]) + __expf(lo0 - u[nt][1]);
            sp1 += __expf(u[nt][2] - hi1) + __expf(u[nt][3] - hi1);
            sn1 += __expf(lo1 - u[nt][2]) + __expf(lo1 - u[nt][3]);
        }
        sp0 = rsum4(sp0); sp1 = rsum4(sp1); sn0 = rsum4(sn0); sn1 = rsum4(sn1);
        float rp0 = 1.f / sp0, rp1 = 1.f / sp1, rn0 = 1.f / sn0, rn1 = 1.f / sn1;
#pragma unroll
        for (int nt = 0; nt < 8; nt++) {
            int j = 4 * nt + tg;
            sPhi[r0 * 68 + j]      = pk(__expf(u[nt][0] - hi0) * rp0, __expf(u[nt][1] - hi0) * rp0);
            sPhi[r0 * 68 + 32 + j] = pk(__expf(lo0 - u[nt][0]) * rn0, __expf(lo0 - u[nt][1]) * rn0);
            sPhi[r1 * 68 + j]      = pk(__expf(u[nt][2] - hi1) * rp1, __expf(u[nt][3] - hi1) * rp1);
            sPhi[r1 * 68 + 32 + j] = pk(__expf(lo1 - u[nt][2]) * rn1, __expf(lo1 - u[nt][3]) * rn1);
        }
    }
    __syncthreads();  // B1: phi ready

    // dS^T[d][f] = sum_s v[s][d] * phi[s][f]; A = v^T (trans), B = phi (trans)
    int mt = w >> 1, nh = w & 1, m0 = 16 * mt, n0 = 64 * nh;
    float acc[8][4] = {};
#pragma unroll
    for (int k0 = 0; k0 < 64; k0 += 16) {
        uint32_t a[4]; ldsm4t(sV, 36, k0, m0, a);
#pragma unroll
        for (int p = 0; p < 4; p++) {
            uint32_t b[4]; ldsm4t(sPhi, 68, k0, n0 + 16 * p, b);
            uint32_t b0[2] = {b[0], b[2]}, b1[2] = {b[1], b[3]};
            mma16(acc[2 * p], a, b0);
            mma16(acc[2 * p + 1], a, b1);
        }
    }
#pragma unroll
    for (int nt = 0; nt < 8; nt++) {
        int jc = (n0 >> 1) + 4 * nt + tg;   // u32 column
        g_dS[sb + (size_t)(m0 + g) * 64 + jc]     = pk(acc[nt][0], acc[nt][1]);
        g_dS[sb + (size_t)(m0 + g + 8) * 64 + jc] = pk(acc[nt][2], acc[nt][3]);
    }
    if (t < 64) {  // Z: column sums of phi (pair 2t, 2t+1)
        float zx = 0.f, zy = 0.f;
#pragma unroll 8
        for (int s = 0; s < 64; s++) {
            float2 f2 = __half22float2(*(__half2*)&sPhi[s * 68 + t]);
            zx += f2.x; zy += f2.y;
        }
        g_dS[sb + 4096 + t] = pk(zx, zy);
    }
}

// ======================= Exclusive prefix scan (fp16 in/out, fp32 carry) =========
__global__ void scanS_kernel() {
    int bh = blockIdx.y;
    int e = blockIdx.x * 256 + threadIdx.x;  // uint4 chain 0..1039
    if (e >= 1040) return;
    uint4* p = (uint4*)g_dS;
    size_t base = (size_t)bh * NB * 1040 + e;
    float r[8] = {};
#pragma unroll 4
    for (int n = 0; n < NB; n++) {
        uint4 x = p[base + (size_t)n * 1040];
        uint4 o;
        o.x = pk(r[0], r[1]); o.y = pk(r[2], r[3]);
        o.z = pk(r[4], r[5]); o.w = pk(r[6], r[7]);
        p[base + (size_t)n * 1040] = o;
        float2 f;
        f = __half22float2(*(__half2*)&x.x); r[0] += f.x; r[1] += f.y;
        f = __half22float2(*(__half2*)&x.y); r[2] += f.x; r[3] += f.y;
        f = __half22float2(*(__half2*)&x.z); r[4] += f.x; r[5] += f.y;
        f = __half22float2(*(__half2*)&x.w); r[6] += f.x; r[7] += f.y;
    }
}

// ======================= Phase 2: outputs ========================================
__global__ void __launch_bounds__(256, 3)
phase2_kernel(const float* __restrict__ Q, const float* __restrict__ K,
              const float* __restrict__ V, const float* __restrict__ alpha,
              float* __restrict__ out) {
    extern __shared__ uint32_t smu[];
    uint32_t* sQ   = smu;           // [64][36] q
    uint32_t* sK   = smu + 2304;    // [64][36] k
    uint32_t* sWV  = smu + 4608;    // [64][36] W^T -> v
    uint32_t* sA   = smu + 6912;    // [64][36] a
    uint32_t* sPhi = smu + 9216;    // [64][68] phi
    uint32_t* sS   = smu + 13568;   // [64][68] S^T (cp.async fp16)
    float*    sZf  = (float*)(smu + 17920);  // 128
    float*    sLd  = (float*)(smu + 18048);  // 64
    float*    sAs  = (float*)(smu + 18112);  // 64  -> 18176 u32 = 72704 B

    int t = threadIdx.x, w = t >> 5, lane = t & 31, g = lane >> 2, tg = lane & 3;
    int bid = blockIdx.x, bh = bid >> 6, n = bid & 63, h = bh & (HH - 1);
    size_t xb = ((size_t)bh * LL + (size_t)n * 64) * 64;
    const uint32_t* SgU = g_dS + (size_t)bid * BLKU;

    // group 0: W^T
#pragma unroll
    for (int i = 0; i < 2; i++) {
        int idx = t + 256 * i;
        int f = idx >> 3, j = idx & 7;
        cp16(sWV + f * 36 + j * 4, g_WT + h * 2048 + f * 32 + j * 4);
    }
    CP_COMMIT();
    // group 1: S^T prefix (fp16, no conversion) — arrives during phase A/B
#pragma unroll
    for (int i = 0; i < 4; i++) {
        int idx = t + 256 * i;              // 0..1023
        int d = idx >> 4, j = idx & 15;
        cp16(sS + d * 68 + j * 4, SgU + d * 64 + j * 4);
    }
    CP_COMMIT();
    if (t < 64) {
        float2 f2 = __half22float2(*(__half2*)&SgU[4096 + t]);
        sZf[2 * t] = f2.x; sZf[2 * t + 1] = f2.y;
    }
#pragma unroll
    for (int i = 0; i < 8; i++) {
        int idx = t + 256 * i;
        int s = idx >> 5, j = idx & 31;
        float2 qx = *(const float2*)&Q[xb + s * 64 + 2 * j];
        float2 kx = *(const float2*)&K[xb + s * 64 + 2 * j];
        sQ[s * 36 + j] = pk(qx.x, qx.y);
        sK[s * 36 + j] = pk(kx.x, kx.y);
    }
    CP_WAIT1();       // W^T done (S may still be in flight)
    __syncthreads();  // B0

    if (w < 4) {
        // u = q @ W, hedgehog phi + lin_den
        int m0 = 16 * w, r0 = m0 + g, r1 = r0 + 8;
        float u[8][4] = {};
#pragma unroll
        for (int k0 = 0; k0 < 64; k0 += 16) {
            uint32_t a[4]; ldsm4(sQ, 36, m0, k0, a);
#pragma unroll
            for (int p = 0; p < 4; p++) {
                uint32_t b[4]; ldsm4(sWV, 36, 16 * p, k0, b);
                uint32_t b0[2] = {b[0], b[2]}, b1[2] = {b[1], b[3]};
                mma16(u[2 * p], a, b0);
                mma16(u[2 * p + 1], a, b1);
            }
        }
        float hi0 = -3e38f, hi1 = -3e38f, lo0 = 3e38f, lo1 = 3e38f;
#pragma unroll
        for (int nt = 0; nt < 8; nt++) {
            hi0 = fmaxf(hi0, fmaxf(u[nt][0], u[nt][1]));
            lo0 = fminf(lo0, fminf(u[nt][0], u[nt][1]));
            hi1 = fmaxf(hi1, fmaxf(u[nt][2], u[nt][3]));
            lo1 = fminf(lo1, fminf(u[nt][2], u[nt][3]));
        }
        hi0 = rmax4(hi0); hi1 = rmax4(hi1);
        lo0 = -rmax4(-lo0); lo1 = -rmax4(-lo1);
        float sp0 = 0.f, sp1 = 0.f, sn0 = 0.f, sn1 = 0.f;
#pragma unroll
        for (int nt = 0; nt < 8; nt++) {
            sp0 += __expf(u[nt][0] - hi0) + __expf(u[nt][1] - hi0);
            sn0 += __expf(lo0 - u[nt][0]) + __expf(lo0 - u[nt][1]);
            sp1 += __expf(u[nt][2] - hi1) + __expf(u[nt][3] - hi1);
            sn1 += __expf(lo1 - u[nt][2]) + __expf(lo1 - u[nt][3]);
        }
        sp0 = rsum4(sp0); sp1 = rsum4(sp1); sn0 = rsum4(sn0); sn1 = rsum4(sn1);
        float rp0 = 1.f / sp0, rp1 = 1.f / sp1, rn0 = 1.f / sn0, rn1 = 1.f / sn1;
        float ld0 = 0.f, ld1 = 0.f;
#pragma unroll
        for (int nt = 0; nt < 8; nt++) {
            int c = 8 * nt + 2 * tg, j = 4 * nt + tg;
            float p00 = __expf(u[nt][0] - hi0) * rp0, p01 = __expf(u[nt][1] - hi0) * rp0;
            float q00 = __expf(lo0 - u[nt][0]) * rn0, q01 = __expf(lo0 - u[nt][1]) * rn0;
            float p10 = __expf(u[nt][2] - hi1) * rp1, p11 = __expf(u[nt][3] - hi1) * rp1;
            float q10 = __expf(lo1 - u[nt][2]) * rn1, q11 = __expf(lo1 - u[nt][3]) * rn1;
            sPhi[r0 * 68 + j]      = pk(p00, p01);
            sPhi[r0 * 68 + 32 + j] = pk(q00, q01);
            sPhi[r1 * 68 + j]      = pk(p10, p11);
            sPhi[r1 * 68 + 32 + j] = pk(q10, q11);
            ld0 += p00 * sZf[c] + p01 * sZf[c + 1] + q00 * sZf[64 + c] + q01 * sZf[65 + c];
            ld1 += p10 * sZf[c] + p11 * sZf[c + 1] + q10 * sZf[64 + c] + q11 * sZf[65 + c];
        }
        ld0 = rsum4(ld0); ld1 = rsum4(ld1);
        if (tg == 0) { sLd[r0] = ld0; sLd[r1] = ld1; }
    } else {
        // scores = q @ k^T, softmax -> a
        int m0 = 16 * (w - 4), r0 = m0 + g, r1 = r0 + 8;
        float sc[8][4] = {};
#pragma unroll
        for (int k0 = 0; k0 < 64; k0 += 16) {
            uint32_t a[4]; ldsm4(sQ, 36, m0, k0, a);
#pragma unroll
            for (int p = 0; p < 4; p++) {
                uint32_t b[4]; ldsm4(sK, 36, 16 * p, k0, b);
                uint32_t b0[2] = {b[0], b[2]}, b1[2] = {b[1], b[3]};
                mma16(sc[2 * p], a, b0);
                mma16(sc[2 * p + 1], a, b1);
            }
        }
        float mx0 = -3e38f, mx1 = -3e38f;
#pragma unroll
        for (int nt = 0; nt < 8; nt++) {
            sc[nt][0] *= 0.125f; sc[nt][1] *= 0.125f;
            sc[nt][2] *= 0.125f; sc[nt][3] *= 0.125f;
            mx0 = fmaxf(mx0, fmaxf(sc[nt][0], sc[nt][1]));
            mx1 = fmaxf(mx1, fmaxf(sc[nt][2], sc[nt][3]));
        }
        mx0 = rmax4(mx0); mx1 = rmax4(mx1);
        float as0 = 0.f, as1 = 0.f;
#pragma unroll
        for (int nt = 0; nt < 8; nt++) {
            sc[nt][0] = __expf(sc[nt][0] - mx0); sc[nt][1] = __expf(sc[nt][1] - mx0);
            sc[nt][2] = __expf(sc[nt][2] - mx1); sc[nt][3] = __expf(sc[nt][3] - mx1);
            as0 += sc[nt][0] + sc[nt][1];
            as1 += sc[nt][2] + sc[nt][3];
        }
        as0 = rsum4(as0); as1 = rsum4(as1);
        if (tg == 0) { sAs[r0] = as0; sAs[r1] = as1; }
#pragma unroll
        for (int nt = 0; nt < 8; nt++) {
            int j = 4 * nt + tg;
            sA[r0 * 36 + j] = pk(sc[nt][0], sc[nt][1]);
            sA[r1 * 36 + j] = pk(sc[nt][2], sc[nt][3]);
        }
    }
    __syncthreads();  // B1: phi, a, sLd, sAs ready; q/k/W^T dead

    // v into the dead W^T buffer
#pragma unroll
    for (int i = 0; i < 8; i++) {
        int idx = t + 256 * i;
        int s = idx >> 5, j = idx & 31;
        float2 vx = *(const float2*)&V[xb + s * 64 + 2 * j];
        sWV[s * 36 + j] = pk(vx.x, vx.y);
    }
    CP_WAIT0();       // S^T arrived long ago
    __syncthreads();  // B2: v + S visible

    int mt = w >> 1, nh = w & 1, m0 = 16 * mt, n0 = 32 * nh, r0 = m0 + g, r1 = r0 + 8;

    // lin = phi @ S (B = S^T rows, non-trans), sm = a @ v (B = v natural, trans)
    float li[4][4] = {}, sm_[4][4] = {};
#pragma unroll
    for (int k0 = 0; k0 < 128; k0 += 16) {
        uint32_t a[4]; ldsm4(sPhi, 68, m0, k0, a);
#pragma unroll
        for (int p = 0; p < 2; p++) {
            uint32_t b[4]; ldsm4(sS, 68, n0 + 16 * p, k0, b);
            uint32_t b0[2] = {b[0], b[2]}, b1[2] = {b[1], b[3]};
            mma16(li[2 * p], a, b0);
            mma16(li[2 * p + 1], a, b1);
        }
    }
#pragma unroll
    for (int k0 = 0; k0 < 64; k0 += 16) {
        uint32_t a[4]; ldsm4(sA, 36, m0, k0, a);
#pragma unroll
        for (int p = 0; p < 2; p++) {
            uint32_t b[4]; ldsm4t(sWV, 36, k0, n0 + 16 * p, b);
            uint32_t b0[2] = {b[0], b[2]}, b1[2] = {b[1], b[3]};
            mma16(sm_[2 * p], a, b0);
            mma16(sm_[2 * p + 1], a, b1);
        }
    }

    float wgt = 1.f / (1.f + __expf(-alpha[h]));
    float den0 = fmaxf(wgt * fmaxf(sAs[r0], EPSV) + fmaxf(sLd[r0], EPSV), EPSV);
    float den1 = fmaxf(wgt * fmaxf(sAs[r1], EPSV) + fmaxf(sLd[r1], EPSV), EPSV);
    float id0 = 1.f / den0, id1 = 1.f / den1;
#pragma unroll
    for (int nt = 0; nt < 4; nt++) {
        int c = n0 + 8 * nt + 2 * tg;
        float2 o0, o1;
        o0.x = (wgt * sm_[nt][0] + li[nt][0]) * id0;
        o0.y = (wgt * sm_[nt][1] + li[nt][1]) * id0;
        o1.x = (wgt * sm_[nt][2] + li[nt][2]) * id1;
        o1.y = (wgt * sm_[nt][3] + li[nt][3]) * id1;
        *(float2*)&out[xb + (size_t)r0 * 64 + c] = o0;
        *(float2*)&out[xb + (size_t)r1 * 64 + c] = o1;
    }
}

extern "C" void kernel_launch(void* const* d_in, const int* in_sizes, int n_in,
                              void* d_out, int out_size) {
    const float* Q = (const float*)d_in[0];
    const float* K = (const float*)d_in[1];
    const float* V = (const float*)d_in[2];
    const float* W = (const float*)d_in[3];
    const float* A = (const float*)d_in[4];
    float* out = (float*)d_out;

    cudaFuncSetAttribute(phase1_kernel, cudaFuncAttributeMaxDynamicSharedMemorySize, 45056);
    cudaFuncSetAttribute(phase2_kernel, cudaFuncAttributeMaxDynamicSharedMemorySize, 72704);

    prep_kernel<<<HH, 256>>>(W);
    phase1_kernel<<<BH * NB, 256, 45056>>>(K, V);
    scanS_kernel<<<dim3(5, BH), 256>>>();
    phase2_kernel<<<BH * NB, 256, 72704>>>(Q, K, V, A, out);
}

// round 12
// speedup vs baseline: 5.3507x; 1.0123x over previous
#include <cuda_runtime.h>
#include <cuda_fp16.h>
#include <cstdint>

#define NB 64
#define HH 16
#define LL 4096
#define BH 32
#define EPSV 1e-6f
#define BLKU 4160   // per-block u32 in g_dS: 64x64 S^T half2 + 64 Z half2

__device__ uint32_t g_dS[(size_t)BH * NB * BLKU];  // 34 MB fp16 scratch
__device__ uint32_t g_WT[HH * 2048];               // W^T fp16 [h][f][d/2]

__device__ __forceinline__ uint32_t pk(float a, float b) {
    __half2 h = __floats2half2_rn(a, b);
    return *(uint32_t*)&h;
}

__device__ __forceinline__ void mma16(float* c, const uint32_t* a, const uint32_t* b) {
    asm volatile(
        "mma.sync.aligned.m16n8k16.row.col.f32.f16.f16.f32 "
        "{%0,%1,%2,%3},{%4,%5,%6,%7},{%8,%9},{%0,%1,%2,%3};"
        : "+f"(c[0]), "+f"(c[1]), "+f"(c[2]), "+f"(c[3])
        : "r"(a[0]), "r"(a[1]), "r"(a[2]), "r"(a[3]), "r"(b[0]), "r"(b[1]));
}

// x4 non-trans: tiles (r0,k0),(r0+8,k0),(r0,k0+8),(r0+8,k0+8); S = half2 array, ld2 in half2
__device__ __forceinline__ void ldsm4(const uint32_t* S, int ld2, int r0, int k0, uint32_t* d) {
    int lane = threadIdx.x & 31, q = lane >> 3, r = lane & 7;
    const uint32_t* p = S + (r0 + r + 8 * (q & 1)) * ld2 + (k0 >> 1) + 4 * (q >> 1);
    unsigned a = (unsigned)__cvta_generic_to_shared(p);
    asm volatile("ldmatrix.sync.aligned.m8n8.x4.shared.b16 {%0,%1,%2,%3},[%4];"
                 : "=r"(d[0]), "=r"(d[1]), "=r"(d[2]), "=r"(d[3]) : "r"(a));
}
// x4 trans from natural [k][n]: tiles (k0,n0),(k0,n0+8),(k0+8,n0),(k0+8,n0+8)
__device__ __forceinline__ void ldsm4t(const uint32_t* S, int ld2, int k0, int n0, uint32_t* d) {
    int lane = threadIdx.x & 31, q = lane >> 3, r = lane & 7;
    const uint32_t* p = S + (k0 + r + 8 * (q >> 1)) * ld2 + (n0 >> 1) + 4 * (q & 1);
    unsigned a = (unsigned)__cvta_generic_to_shared(p);
    asm volatile("ldmatrix.sync.aligned.m8n8.x4.trans.shared.b16 {%0,%1,%2,%3},[%4];"
                 : "=r"(d[0]), "=r"(d[1]), "=r"(d[2]), "=r"(d[3]) : "r"(a));
}

__device__ __forceinline__ float rmax4(float x) {
    x = fmaxf(x, __shfl_xor_sync(0xffffffffu, x, 1));
    x = fmaxf(x, __shfl_xor_sync(0xffffffffu, x, 2));
    return x;
}
__device__ __forceinline__ float rsum4(float x) {
    x += __shfl_xor_sync(0xffffffffu, x, 1);
    x += __shfl_xor_sync(0xffffffffu, x, 2);
    return x;
}

__device__ __forceinline__ void cp16(void* dst_smem, const void* src_g) {
    unsigned d = (unsigned)__cvta_generic_to_shared(dst_smem);
    asm volatile("cp.async.cg.shared.global [%0], [%1], 16;" :: "r"(d), "l"(src_g));
}
#define CP_COMMIT() asm volatile("cp.async.commit_group;")
#define CP_WAIT0()  asm volatile("cp.async.wait_group 0;")
#define CP_WAIT1()  asm volatile("cp.async.wait_group 1;")

// ======================= Prep: W^T -> fp16 global ================================
__global__ void prep_kernel(const float* __restrict__ W) {
    int h = blockIdx.x, t = threadIdx.x;
    const float* Wh = W + h * 4096;
#pragma unroll
    for (int i = 0; i < 8; i++) {
        int idx = t + 256 * i;              // 0..2047
        int f = idx >> 5, j = idx & 31;     // WT[f][d-pair j]
        g_WT[h * 2048 + f * 32 + j] = pk(Wh[(2 * j) * 64 + f], Wh[(2 * j + 1) * 64 + f]);
    }
}

// ======================= Phase 1: fp16 S^T block deltas + Z ======================
__global__ void __launch_bounds__(256, 3)
phase1_kernel(const float* __restrict__ K, const float* __restrict__ V) {
    extern __shared__ uint32_t smu[];
    uint32_t* sK   = smu;          // [64][36] k
    uint32_t* sV   = smu + 2304;   // [64][36] v
    uint32_t* sWT  = smu + 4608;   // [64][36] W^T
    uint32_t* sPhi = smu + 6912;   // [64][68] phi
    float*    pex  = (float*)(smu + 11264);  // 512: pmax|pmin|psp|psn  -> 47104 B

    int t = threadIdx.x, w = t >> 5, lane = t & 31, g = lane >> 2, tg = lane & 3;
    int bid = blockIdx.x, bh = bid >> 6, n = bid & 63, h = bh & (HH - 1);
    size_t xb = ((size_t)bh * LL + (size_t)n * 64) * 64;
    size_t sb = (size_t)bid * BLKU;

#pragma unroll
    for (int i = 0; i < 2; i++) {
        int idx = t + 256 * i;              // 0..511
        int f = idx >> 3, j = idx & 7;
        cp16(sWT + f * 36 + j * 4, g_WT + h * 2048 + f * 32 + j * 4);
    }
    CP_COMMIT();
#pragma unroll
    for (int i = 0; i < 4; i++) {
        int idx = t + 256 * i;              // 0..1023
        int s = idx >> 4, j = idx & 15;
        float4 kx = *(const float4*)&K[xb + s * 64 + 4 * j];
        float4 vx = *(const float4*)&V[xb + s * 64 + 4 * j];
        sK[s * 36 + 2 * j]     = pk(kx.x, kx.y);
        sK[s * 36 + 2 * j + 1] = pk(kx.z, kx.w);
        sV[s * 36 + 2 * j]     = pk(vx.x, vx.y);
        sV[s * 36 + 2 * j + 1] = pk(vx.z, vx.w);
    }
    CP_WAIT0();
    __syncthreads();  // B0

    // u = k @ W spread over ALL 8 warps: warp = (m-tile mt, n-half nh)
    float* pmax = pex, *pmin = pex + 128, *psp = pex + 256, *psn = pex + 384;
    int mt = w >> 1, nh = w & 1, m0 = 16 * mt, r0 = m0 + g, r1 = r0 + 8;
    {
        float u[4][4] = {};
#pragma unroll
        for (int k0 = 0; k0 < 64; k0 += 16) {
            uint32_t a[4]; ldsm4(sK, 36, m0, k0, a);
#pragma unroll
            for (int p = 0; p < 2; p++) {
                uint32_t b[4]; ldsm4(sWT, 36, 16 * (2 * nh + p), k0, b);
                uint32_t b0[2] = {b[0], b[2]}, b1[2] = {b[1], b[3]};
                mma16(u[2 * p], a, b0);
                mma16(u[2 * p + 1], a, b1);
            }
        }
        float hi0 = -3e38f, hi1 = -3e38f, lo0 = 3e38f, lo1 = 3e38f;
#pragma unroll
        for (int nt = 0; nt < 4; nt++) {
            hi0 = fmaxf(hi0, fmaxf(u[nt][0], u[nt][1]));
            lo0 = fminf(lo0, fminf(u[nt][0], u[nt][1]));
            hi1 = fmaxf(hi1, fmaxf(u[nt][2], u[nt][3]));
            lo1 = fminf(lo1, fminf(u[nt][2], u[nt][3]));
        }
        hi0 = rmax4(hi0); hi1 = rmax4(hi1);
        lo0 = -rmax4(-lo0); lo1 = -rmax4(-lo1);
        if (tg == 0) {
            pmax[r0 * 2 + nh] = hi0; pmax[r1 * 2 + nh] = hi1;
            pmin[r0 * 2 + nh] = lo0; pmin[r1 * 2 + nh] = lo1;
        }
        __syncthreads();  // B0a: partial max/min ready
        float HI0 = fmaxf(pmax[r0 * 2], pmax[r0 * 2 + 1]);
        float HI1 = fmaxf(pmax[r1 * 2], pmax[r1 * 2 + 1]);
        float LO0 = fminf(pmin[r0 * 2], pmin[r0 * 2 + 1]);
        float LO1 = fminf(pmin[r1 * 2], pmin[r1 * 2 + 1]);
        float sp0 = 0.f, sp1 = 0.f, sn0 = 0.f, sn1 = 0.f;
#pragma unroll
        for (int nt = 0; nt < 4; nt++) {
            sp0 += __expf(u[nt][0] - HI0) + __expf(u[nt][1] - HI0);
            sn0 += __expf(LO0 - u[nt][0]) + __expf(LO0 - u[nt][1]);
            sp1 += __expf(u[nt][2] - HI1) + __expf(u[nt][3] - HI1);
            sn1 += __expf(LO1 - u[nt][2]) + __expf(LO1 - u[nt][3]);
        }
        sp0 = rsum4(sp0); sp1 = rsum4(sp1); sn0 = rsum4(sn0); sn1 = rsum4(sn1);
        if (tg == 0) {
            psp[r0 * 2 + nh] = sp0; psp[r1 * 2 + nh] = sp1;
            psn[r0 * 2 + nh] = sn0; psn[r1 * 2 + nh] = sn1;
        }
        __syncthreads();  // B0b: partial sums ready
        float rp0 = 1.f / (psp[r0 * 2] + psp[r0 * 2 + 1]);
        float rp1 = 1.f / (psp[r1 * 2] + psp[r1 * 2 + 1]);
        float rn0 = 1.f / (psn[r0 * 2] + psn[r0 * 2 + 1]);
        float rn1 = 1.f / (psn[r1 * 2] + psn[r1 * 2 + 1]);
#pragma unroll
        for (int nt = 0; nt < 4; nt++) {
            int j = 16 * nh + 4 * nt + tg;
            sPhi[r0 * 68 + j]      = pk(__expf(u[nt][0] - HI0) * rp0, __expf(u[nt][1] - HI0) * rp0);
            sPhi[r0 * 68 + 32 + j] = pk(__expf(LO0 - u[nt][0]) * rn0, __expf(LO0 - u[nt][1]) * rn0);
            sPhi[r1 * 68 + j]      = pk(__expf(u[nt][2] - HI1) * rp1, __expf(u[nt][3] - HI1) * rp1);
            sPhi[r1 * 68 + 32 + j] = pk(__expf(LO1 - u[nt][2]) * rn1, __expf(LO1 - u[nt][3]) * rn1);
        }
    }
    __syncthreads();  // B1: phi ready

    // dS^T[d][f] = sum_s v[s][d] * phi[s][f]; A = v^T (trans), B = phi (trans)
    int n0 = 64 * nh;
    float acc[8][4] = {};
#pragma unroll
    for (int k0 = 0; k0 < 64; k0 += 16) {
        uint32_t a[4]; ldsm4t(sV, 36, k0, m0, a);
#pragma unroll
        for (int p = 0; p < 4; p++) {
            uint32_t b[4]; ldsm4t(sPhi, 68, k0, n0 + 16 * p, b);
            uint32_t b0[2] = {b[0], b[2]}, b1[2] = {b[1], b[3]};
            mma16(acc[2 * p], a, b0);
            mma16(acc[2 * p + 1], a, b1);
        }
    }
#pragma unroll
    for (int nt = 0; nt < 8; nt++) {
        int jc = (n0 >> 1) + 4 * nt + tg;   // u32 column
        g_dS[sb + (size_t)(m0 + g) * 64 + jc]     = pk(acc[nt][0], acc[nt][1]);
        g_dS[sb + (size_t)(m0 + g + 8) * 64 + jc] = pk(acc[nt][2], acc[nt][3]);
    }
    if (t < 64) {  // Z: column sums of phi (pair 2t, 2t+1)
        float zx = 0.f, zy = 0.f;
#pragma unroll 8
        for (int s = 0; s < 64; s++) {
            float2 f2 = __half22float2(*(__half2*)&sPhi[s * 68 + t]);
            zx += f2.x; zy += f2.y;
        }
        g_dS[sb + 4096 + t] = pk(zx, zy);
    }
}

// ======================= Exclusive prefix scan (fp16 in/out, fp32 carry) =========
__global__ void scanS_kernel() {
    int bh = blockIdx.y;
    int e = blockIdx.x * 256 + threadIdx.x;  // uint4 chain 0..1039
    if (e >= 1040) return;
    uint4* p = (uint4*)g_dS;
    size_t base = (size_t)bh * NB * 1040 + e;
    float r[8] = {};
#pragma unroll 4
    for (int n = 0; n < NB; n++) {
        uint4 x = p[base + (size_t)n * 1040];
        uint4 o;
        o.x = pk(r[0], r[1]); o.y = pk(r[2], r[3]);
        o.z = pk(r[4], r[5]); o.w = pk(r[6], r[7]);
        p[base + (size_t)n * 1040] = o;
        float2 f;
        f = __half22float2(*(__half2*)&x.x); r[0] += f.x; r[1] += f.y;
        f = __half22float2(*(__half2*)&x.y); r[2] += f.x; r[3] += f.y;
        f = __half22float2(*(__half2*)&x.z); r[4] += f.x; r[5] += f.y;
        f = __half22float2(*(__half2*)&x.w); r[6] += f.x; r[7] += f.y;
    }
}

// ======================= Phase 2: outputs ========================================
__global__ void __launch_bounds__(256, 3)
phase2_kernel(const float* __restrict__ Q, const float* __restrict__ K,
              const float* __restrict__ V, const float* __restrict__ alpha,
              float* __restrict__ out) {
    extern __shared__ uint32_t smu[];
    uint32_t* sQ   = smu;           // [64][36] q
    uint32_t* sK   = smu + 2304;    // [64][36] k
    uint32_t* sWV  = smu + 4608;    // [64][36] W^T -> v
    uint32_t* sA   = smu + 6912;    // [64][36] a
    uint32_t* sPhi = smu + 9216;    // [64][68] phi
    uint32_t* sS   = smu + 13568;   // [64][68] S^T (cp.async fp16)
    float*    sZf  = (float*)(smu + 17920);  // 128
    float*    sLd  = (float*)(smu + 18048);  // 64
    float*    sAs  = (float*)(smu + 18112);  // 64  -> 18176 u32 = 72704 B

    int t = threadIdx.x, w = t >> 5, lane = t & 31, g = lane >> 2, tg = lane & 3;
    int bid = blockIdx.x, bh = bid >> 6, n = bid & 63, h = bh & (HH - 1);
    size_t xb = ((size_t)bh * LL + (size_t)n * 64) * 64;
    const uint32_t* SgU = g_dS + (size_t)bid * BLKU;

    // group 0: W^T
#pragma unroll
    for (int i = 0; i < 2; i++) {
        int idx = t + 256 * i;
        int f = idx >> 3, j = idx & 7;
        cp16(sWV + f * 36 + j * 4, g_WT + h * 2048 + f * 32 + j * 4);
    }
    CP_COMMIT();
    // group 1: S^T prefix (fp16, no conversion) — arrives during phase A/B
#pragma unroll
    for (int i = 0; i < 4; i++) {
        int idx = t + 256 * i;              // 0..1023
        int d = idx >> 4, j = idx & 15;
        cp16(sS + d * 68 + j * 4, SgU + d * 64 + j * 4);
    }
    CP_COMMIT();
    if (t < 64) {
        float2 f2 = __half22float2(*(__half2*)&SgU[4096 + t]);
        sZf[2 * t] = f2.x; sZf[2 * t + 1] = f2.y;
    }
#pragma unroll
    for (int i = 0; i < 4; i++) {
        int idx = t + 256 * i;              // 0..1023
        int s = idx >> 4, j = idx & 15;
        float4 qx = *(const float4*)&Q[xb + s * 64 + 4 * j];
        float4 kx = *(const float4*)&K[xb + s * 64 + 4 * j];
        sQ[s * 36 + 2 * j]     = pk(qx.x, qx.y);
        sQ[s * 36 + 2 * j + 1] = pk(qx.z, qx.w);
        sK[s * 36 + 2 * j]     = pk(kx.x, kx.y);
        sK[s * 36 + 2 * j + 1] = pk(kx.z, kx.w);
    }
    CP_WAIT1();       // W^T done (S may still be in flight)
    __syncthreads();  // B0

    if (w < 4) {
        // u = q @ W, hedgehog phi + lin_den
        int m0 = 16 * w, r0 = m0 + g, r1 = r0 + 8;
        float u[8][4] = {};
#pragma unroll
        for (int k0 = 0; k0 < 64; k0 += 16) {
            uint32_t a[4]; ldsm4(sQ, 36, m0, k0, a);
#pragma unroll
            for (int p = 0; p < 4; p++) {
                uint32_t b[4]; ldsm4(sWV, 36, 16 * p, k0, b);
                uint32_t b0[2] = {b[0], b[2]}, b1[2] = {b[1], b[3]};
                mma16(u[2 * p], a, b0);
                mma16(u[2 * p + 1], a, b1);
            }
        }
        float hi0 = -3e38f, hi1 = -3e38f, lo0 = 3e38f, lo1 = 3e38f;
#pragma unroll
        for (int nt = 0; nt < 8; nt++) {
            hi0 = fmaxf(hi0, fmaxf(u[nt][0], u[nt][1]));
            lo0 = fminf(lo0, fminf(u[nt][0], u[nt][1]));
            hi1 = fmaxf(hi1, fmaxf(u[nt][2], u[nt][3]));
            lo1 = fminf(lo1, fminf(u[nt][2], u[nt][3]));
        }
        hi0 = rmax4(hi0); hi1 = rmax4(hi1);
        lo0 = -rmax4(-lo0); lo1 = -rmax4(-lo1);
        float sp0 = 0.f, sp1 = 0.f, sn0 = 0.f, sn1 = 0.f;
#pragma unroll
        for (int nt = 0; nt < 8; nt++) {
            sp0 += __expf(u[nt][0] - hi0) + __expf(u[nt][1] - hi0);
            sn0 += __expf(lo0 - u[nt][0]) + __expf(lo0 - u[nt][1]);
            sp1 += __expf(u[nt][2] - hi1) + __expf(u[nt][3] - hi1);
            sn1 += __expf(lo1 - u[nt][2]) + __expf(lo1 - u[nt][3]);
        }
        sp0 = rsum4(sp0); sp1 = rsum4(sp1); sn0 = rsum4(sn0); sn1 = rsum4(sn1);
        float rp0 = 1.f / sp0, rp1 = 1.f / sp1, rn0 = 1.f / sn0, rn1 = 1.f / sn1;
        float ld0 = 0.f, ld1 = 0.f;
#pragma unroll
        for (int nt = 0; nt < 8; nt++) {
            int c = 8 * nt + 2 * tg, j = 4 * nt + tg;
            float p00 = __expf(u[nt][0] - hi0) * rp0, p01 = __expf(u[nt][1] - hi0) * rp0;
            float q00 = __expf(lo0 - u[nt][0]) * rn0, q01 = __expf(lo0 - u[nt][1]) * rn0;
            float p10 = __expf(u[nt][2] - hi1) * rp1, p11 = __expf(u[nt][3] - hi1) * rp1;
            float q10 = __expf(lo1 - u[nt][2]) * rn1, q11 = __expf(lo1 - u[nt][3]) * rn1;
            sPhi[r0 * 68 + j]      = pk(p00, p01);
            sPhi[r0 * 68 + 32 + j] = pk(q00, q01);
            sPhi[r1 * 68 + j]      = pk(p10, p11);
            sPhi[r1 * 68 + 32 + j] = pk(q10, q11);
            ld0 += p00 * sZf[c] + p01 * sZf[c + 1] + q00 * sZf[64 + c] + q01 * sZf[65 + c];
            ld1 += p10 * sZf[c] + p11 * sZf[c + 1] + q10 * sZf[64 + c] + q11 * sZf[65 + c];
        }
        ld0 = rsum4(ld0); ld1 = rsum4(ld1);
        if (tg == 0) { sLd[r0] = ld0; sLd[r1] = ld1; }
    } else {
        // scores = q @ k^T, softmax -> a
        int m0 = 16 * (w - 4), r0 = m0 + g, r1 = r0 + 8;
        float sc[8][4] = {};
#pragma unroll
        for (int k0 = 0; k0 < 64; k0 += 16) {
            uint32_t a[4]; ldsm4(sQ, 36, m0, k0, a);
#pragma unroll
            for (int p = 0; p < 4; p++) {
                uint32_t b[4]; ldsm4(sK, 36, 16 * p, k0, b);
                uint32_t b0[2] = {b[0], b[2]}, b1[2] = {b[1], b[3]};
                mma16(sc[2 * p], a, b0);
                mma16(sc[2 * p + 1], a, b1);
            }
        }
        float mx0 = -3e38f, mx1 = -3e38f;
#pragma unroll
        for (int nt = 0; nt < 8; nt++) {
            sc[nt][0] *= 0.125f; sc[nt][1] *= 0.125f;
            sc[nt][2] *= 0.125f; sc[nt][3] *= 0.125f;
            mx0 = fmaxf(mx0, fmaxf(sc[nt][0], sc[nt][1]));
            mx1 = fmaxf(mx1, fmaxf(sc[nt][2], sc[nt][3]));
        }
        mx0 = rmax4(mx0); mx1 = rmax4(mx1);
        float as0 = 0.f, as1 = 0.f;
#pragma unroll
        for (int nt = 0; nt < 8; nt++) {
            sc[nt][0] = __expf(sc[nt][0] - mx0); sc[nt][1] = __expf(sc[nt][1] - mx0);
            sc[nt][2] = __expf(sc[nt][2] - mx1); sc[nt][3] = __expf(sc[nt][3] - mx1);
            as0 += sc[nt][0] + sc[nt][1];
            as1 += sc[nt][2] + sc[nt][3];
        }
        as0 = rsum4(as0); as1 = rsum4(as1);
        if (tg == 0) { sAs[r0] = as0; sAs[r1] = as1; }
#pragma unroll
        for (int nt = 0; nt < 8; nt++) {
            int j = 4 * nt + tg;
            sA[r0 * 36 + j] = pk(sc[nt][0], sc[nt][1]);
            sA[r1 * 36 + j] = pk(sc[nt][2], sc[nt][3]);
        }
    }
    __syncthreads();  // B1: phi, a, sLd, sAs ready; q/k/W^T dead

    // v into the dead W^T buffer
#pragma unroll
    for (int i = 0; i < 4; i++) {
        int idx = t + 256 * i;
        int s = idx >> 4, j = idx & 15;
        float4 vx = *(const float4*)&V[xb + s * 64 + 4 * j];
        sWV[s * 36 + 2 * j]     = pk(vx.x, vx.y);
        sWV[s * 36 + 2 * j + 1] = pk(vx.z, vx.w);
    }
    CP_WAIT0();       // S^T arrived long ago
    __syncthreads();  // B2: v + S visible

    int mt = w >> 1, nh = w & 1, m0 = 16 * mt, n0 = 32 * nh, r0 = m0 + g, r1 = r0 + 8;

    // lin = phi @ S (B = S^T rows, non-trans), sm = a @ v (B = v natural, trans)
    float li[4][4] = {}, sm_[4][4] = {};
#pragma unroll
    for (int k0 = 0; k0 < 128; k0 += 16) {
        uint32_t a[4]; ldsm4(sPhi, 68, m0, k0, a);
#pragma unroll
        for (int p = 0; p < 2; p++) {
            uint32_t b[4]; ldsm4(sS, 68, n0 + 16 * p, k0, b);
            uint32_t b0[2] = {b[0], b[2]}, b1[2] = {b[1], b[3]};
            mma16(li[2 * p], a, b0);
            mma16(li[2 * p + 1], a, b1);
        }
    }
#pragma unroll
    for (int k0 = 0; k0 < 64; k0 += 16) {
        uint32_t a[4]; ldsm4(sA, 36, m0, k0, a);
#pragma unroll
        for (int p = 0; p < 2; p++) {
            uint32_t b[4]; ldsm4t(sWV, 36, k0, n0 + 16 * p, b);
            uint32_t b0[2] = {b[0], b[2]}, b1[2] = {b[1], b[3]};
            mma16(sm_[2 * p], a, b0);
            mma16(sm_[2 * p + 1], a, b1);
        }
    }

    float wgt = 1.f / (1.f + __expf(-alpha[h]));
    float den0 = fmaxf(wgt * fmaxf(sAs[r0], EPSV) + fmaxf(sLd[r0], EPSV), EPSV);
    float den1 = fmaxf(wgt * fmaxf(sAs[r1], EPSV) + fmaxf(sLd[r1], EPSV), EPSV);
    float id0 = 1.f / den0, id1 = 1.f / den1;
#pragma unroll
    for (int nt = 0; nt < 4; nt++) {
        int c = n0 + 8 * nt + 2 * tg;
        float2 o0, o1;
        o0.x = (wgt * sm_[nt][0] + li[nt][0]) * id0;
        o0.y = (wgt * sm_[nt][1] + li[nt][1]) * id0;
        o1.x = (wgt * sm_[nt][2] + li[nt][2]) * id1;
        o1.y = (wgt * sm_[nt][3] + li[nt][3]) * id1;
        *(float2*)&out[xb + (size_t)r0 * 64 + c] = o0;
        *(float2*)&out[xb + (size_t)r1 * 64 + c] = o1;
    }
}

extern "C" void kernel_launch(void* const* d_in, const int* in_sizes, int n_in,
                              void* d_out, int out_size) {
    const float* Q = (const float*)d_in[0];
    const float* K = (const float*)d_in[1];
    const float* V = (const float*)d_in[2];
    const float* W = (const float*)d_in[3];
    const float* A = (const float*)d_in[4];
    float* out = (float*)d_out;

    cudaFuncSetAttribute(phase1_kernel, cudaFuncAttributeMaxDynamicSharedMemorySize, 47104);
    cudaFuncSetAttribute(phase2_kernel, cudaFuncAttributeMaxDynamicSharedMemorySize, 72704);

    prep_kernel<<<HH, 256>>>(W);
    phase1_kernel<<<BH * NB, 256, 47104>>>(K, V);
    scanS_kernel<<<dim3(5, BH), 256>>>();
    phase2_kernel<<<BH * NB, 256, 72704>>>(Q, K, V, A, out);
}